// round 3
// baseline (speedup 1.0000x reference)
#include <cuda_runtime.h>

#define LSZ   4096
#define BATCH 64
#define R1    48
#define R2    16
#define NIN   1024
#define FCN   512
#define NCLS  10

// ---------------- scratch (device globals; no allocation allowed) ----------------
__device__ float g_da1[LSZ], g_db1[LSZ], g_da2[LSZ], g_db2[LSZ];
__device__ float g_Gt1[R1*LSZ], g_Ht1[R1*LSZ];
__device__ float g_Gt2[R2*LSZ], g_Ht2[R2*LSZ];
__device__ float g_Mrot[(size_t)LSZ*LSZ];   // Qrot, 64 MB
__device__ float g_M0[(size_t)LSZ*LSZ];     // M0 standard layout, 64 MB
__device__ float g_tot[32*LSZ];
__device__ float g_z1[BATCH*LSZ];
__device__ float g_z2[BATCH*LSZ];
__device__ float g_h2[BATCH*LSZ];
__device__ float g_Ypart[8*BATCH*LSZ];      // split-K partials, 8 MB

// ---------------- cumprod scan: d[0]=1, d[j]=prod_{k<j} subd[k] ----------------
__global__ void scan_kernel(const float* __restrict__ sA1, const float* __restrict__ sB1,
                            const float* __restrict__ sA2, const float* __restrict__ sB2) {
    const float* src; float* dst;
    if      (blockIdx.x == 0) { src = sA1; dst = g_da1; }
    else if (blockIdx.x == 1) { src = sB1; dst = g_db1; }
    else if (blockIdx.x == 2) { src = sA2; dst = g_da2; }
    else                      { src = sB2; dst = g_db2; }

    __shared__ float part[1024];
    int tid = threadIdx.x;
    float v[4]; float p = 1.f;
#pragma unroll
    for (int j = 0; j < 4; j++) {
        int idx = tid * 4 + j;
        float s = (idx < LSZ - 1) ? src[idx] : 1.f;
        p *= s; v[j] = p;
    }
    part[tid] = p; __syncthreads();
    for (int off = 1; off < 1024; off <<= 1) {
        float x = part[tid];
        float m = (tid >= off) ? part[tid - off] : 1.f;
        __syncthreads();
        part[tid] = x * m;
        __syncthreads();
    }
    float excl = (tid == 0) ? 1.f : part[tid - 1];
    if (tid == 0) dst[0] = 1.f;
#pragma unroll
    for (int j = 0; j < 4; j++) {
        int idx = tid * 4 + j;
        if (idx < LSZ - 1) dst[idx + 1] = excl * v[j];
    }
}

// ---------------- prep: Gt=G/da, Ht=H/db, z1 = db1 * pad(x) ----------------
__global__ void prep_kernel(const float* __restrict__ G1, const float* __restrict__ H1,
                            const float* __restrict__ G2, const float* __restrict__ H2,
                            const float* __restrict__ x) {
    int tid = blockIdx.x * blockDim.x + threadIdx.x;
    int j = tid & (LSZ - 1);
    if (tid < R1 * LSZ) {
        g_Gt1[tid] = G1[tid] / g_da1[j];
        g_Ht1[tid] = H1[tid] / g_db1[j];
    }
    if (tid < R2 * LSZ) {
        g_Gt2[tid] = G2[tid] / g_da2[j];
        g_Ht2[tid] = H2[tid] / g_db2[j];
    }
    if (tid < BATCH * LSZ) {
        int b = tid >> 12;
        g_z1[tid] = (j < NIN) ? x[b * NIN + j] * g_db1[j] : 0.f;
    }
}

// ---------------- Qrot = Gt^T Ht in rotated layout + reset-aware tile totals ----------------
// Qrot[t][c] = sum_i Gt[i][t] * Ht[i][(t+c) mod n]
// tile: 128 t (blockIdx.y) x 128 c (blockIdx.x); 256 thr; micro 8x8 contiguous (t=ty*8+u, c=tx*8+v)
template <int R>
__global__ __launch_bounds__(256, 2) void qrot_kernel() {
    const float* __restrict__ Gt = (R == R1) ? g_Gt1 : g_Gt2;
    const float* __restrict__ Ht = (R == R1) ? g_Ht1 : g_Ht2;
    extern __shared__ float sh[];
    float* sG  = sh;               // R*128
    float* sH  = sG + R * 128;     // R*260 (rows of 256, pad to 260 for alignment)
    float* red = sH + R * 260;     // 16*128

    int t0 = blockIdx.y << 7, c0 = blockIdx.x << 7;
    int base = t0 + c0;
    for (int idx = threadIdx.x; idx < R * 128; idx += 256) {
        int i = idx >> 7, tt = idx & 127;
        sG[idx] = Gt[i * LSZ + t0 + tt];
    }
    for (int idx = threadIdx.x; idx < R * 256; idx += 256) {
        int i = idx >> 8, s = idx & 255;
        sH[i * 260 + s] = Ht[i * LSZ + ((base + s) & (LSZ - 1))];
    }
    __syncthreads();

    int tx = threadIdx.x & 15, ty = threadIdx.x >> 4;
    float acc[8][8];
#pragma unroll
    for (int u = 0; u < 8; u++)
#pragma unroll
        for (int v = 0; v < 8; v++) acc[u][v] = 0.f;

    for (int i = 0; i < R; i++) {
        float a[8], h[16];
        ((float4*)a)[0] = *(const float4*)&sG[i * 128 + ty * 8];
        ((float4*)a)[1] = *(const float4*)&sG[i * 128 + ty * 8 + 4];
        int hb = i * 260 + 8 * (tx + ty);
#pragma unroll
        for (int j = 0; j < 4; j++)
            ((float4*)h)[j] = *(const float4*)&sH[hb + 4 * j];
#pragma unroll
        for (int u = 0; u < 8; u++)
#pragma unroll
            for (int v = 0; v < 8; v++) acc[u][v] = fmaf(a[u], h[u + v], acc[u][v]);
    }

    // store Qrot (float4) + reset-aware column partials
    float colsum[8];
#pragma unroll
    for (int v = 0; v < 8; v++) colsum[v] = 0.f;
#pragma unroll
    for (int u = 0; u < 8; u++) {
        int t = t0 + ty * 8 + u;
        float4 q0 = make_float4(acc[u][0], acc[u][1], acc[u][2], acc[u][3]);
        float4 q1 = make_float4(acc[u][4], acc[u][5], acc[u][6], acc[u][7]);
        *(float4*)&g_Mrot[(size_t)t * LSZ + c0 + tx * 8]     = q0;
        *(float4*)&g_Mrot[(size_t)t * LSZ + c0 + tx * 8 + 4] = q1;
#pragma unroll
        for (int v = 0; v < 8; v++) {
            int c = c0 + tx * 8 + v;
            int s0 = (LSZ - c) & (LSZ - 1);      // diagonal reset row for column c
            bool inc = (s0 <= t0) || (s0 >= t0 + 128) || (t >= s0);
            if (inc) colsum[v] += acc[u][v];
        }
    }
#pragma unroll
    for (int v = 0; v < 8; v++) red[ty * 128 + tx * 8 + v] = colsum[v];
    __syncthreads();
    if (threadIdx.x < 128) {
        float s = 0.f;
#pragma unroll
        for (int y = 0; y < 16; y++) s += red[y * 128 + threadIdx.x];
        g_tot[blockIdx.y * LSZ + c0 + threadIdx.x] = s;
    }
}

// ---------------- segmented diagonal cumsum, writes M0 in STANDARD [t][w] layout --------------
// Also computes its own prefix of tile totals (g_tot is L2-resident) — no scanP pass.
__global__ void cumsum_kernel() {
    int c = blockIdx.x * 256 + threadIdx.x;
    int k = blockIdx.y;
    int t0 = k << 7;
    int s0 = (LSZ - c) & (LSZ - 1);
    int ks0 = s0 >> 7;
    int kstart = (s0 <= t0) ? ks0 : 0;
    float acc = 0.f;
    for (int k2 = kstart; k2 < k; k2++) acc += g_tot[k2 * LSZ + c];

    size_t qidx = (size_t)t0 * LSZ + c;
#pragma unroll 4
    for (int r = 0; r < 128; r++) {
        int t = t0 + r;
        float q = g_Mrot[qidx + (size_t)r * LSZ];
        if (t == s0) acc = 0.f;
        acc += q;
        g_M0[(size_t)t * LSZ + ((t + c) & (LSZ - 1))] = acc;  // un-rotate on write (coalesced)
    }
}

// ---------------- main GEMM: Ypart[slice][b][t] = sum_{w in slice} M0[t][w] z[b][w] ----------
// 128 t x 64 b block tile, K-slice 512. micro: t = tx+16u (8), b = ty+16v (4). float4 along kk.
__global__ __launch_bounds__(256, 2) void skewgemm_kernel(int layer) {
    const float* __restrict__ z = layer ? g_z2 : g_z1;
    extern __shared__ float sh[];
    float* sM = sh;                 // 128 x 132
    float* sz = sh + 128 * 132;     // 64 x 132
    int t0  = blockIdx.x << 7;
    int w0b = blockIdx.y << 9;
    int tx = threadIdx.x & 15, ty = threadIdx.x >> 4;
    float acc[8][4];
#pragma unroll
    for (int u = 0; u < 8; u++)
#pragma unroll
        for (int v = 0; v < 4; v++) acc[u][v] = 0.f;

    for (int wc = 0; wc < 512; wc += 128) {
        int w0 = w0b + wc;
        for (int idx = threadIdx.x; idx < 128 * 32; idx += 256) {
            int row = idx >> 5, cc = idx & 31;
            float4 m4 = *(const float4*)&g_M0[(size_t)(t0 + row) * LSZ + w0 + 4 * cc];
            *(float4*)&sM[row * 132 + 4 * cc] = m4;
        }
        for (int idx = threadIdx.x; idx < 64 * 32; idx += 256) {
            int b = idx >> 5, cc = idx & 31;
            float4 z4 = *(const float4*)&z[b * LSZ + w0 + 4 * cc];
            *(float4*)&sz[b * 132 + 4 * cc] = z4;
        }
        __syncthreads();
#pragma unroll 2
        for (int kk = 0; kk < 128; kk += 4) {
            float4 a4[8], z4[4];
#pragma unroll
            for (int u = 0; u < 8; u++) a4[u] = *(const float4*)&sM[(tx + 16 * u) * 132 + kk];
#pragma unroll
            for (int v = 0; v < 4; v++) z4[v] = *(const float4*)&sz[(ty + 16 * v) * 132 + kk];
#pragma unroll
            for (int u = 0; u < 8; u++)
#pragma unroll
                for (int v = 0; v < 4; v++) {
                    acc[u][v] = fmaf(a4[u].x, z4[v].x, acc[u][v]);
                    acc[u][v] = fmaf(a4[u].y, z4[v].y, acc[u][v]);
                    acc[u][v] = fmaf(a4[u].z, z4[v].z, acc[u][v]);
                    acc[u][v] = fmaf(a4[u].w, z4[v].w, acc[u][v]);
                }
        }
        __syncthreads();
    }
#pragma unroll
    for (int u = 0; u < 8; u++) {
        int t = t0 + tx + 16 * u;
#pragma unroll
        for (int v = 0; v < 4; v++) {
            int b = ty + 16 * v;
            g_Ypart[((size_t)blockIdx.y * BATCH + b) * LSZ + t] = acc[u][v];
        }
    }
}

// ---------------- epilogue: reduce split-K, bias+relu+da; layer0 also folds db2 ----------------
__global__ void epilogue_kernel(const float* __restrict__ bias, int layer) {
    int i4 = blockIdx.x * 256 + threadIdx.x;          // float4 index over BATCH*LSZ
    if (i4 >= BATCH * LSZ / 4) return;
    const float4* Yp = (const float4*)g_Ypart;
    float4 s = Yp[i4];
#pragma unroll
    for (int k = 1; k < 8; k++) {
        float4 p = Yp[(size_t)k * (BATCH * LSZ / 4) + i4];
        s.x += p.x; s.y += p.y; s.z += p.z; s.w += p.w;
    }
    int t = (i4 * 4) & (LSZ - 1);
    const float* da = layer ? g_da2 : g_da1;
    float4 dav = *(const float4*)&da[t];
    float4 bv  = *(const float4*)&bias[t];
    float4 h;
    h.x = fmaxf(dav.x * s.x + bv.x, 0.f);
    h.y = fmaxf(dav.y * s.y + bv.y, 0.f);
    h.z = fmaxf(dav.z * s.z + bv.z, 0.f);
    h.w = fmaxf(dav.w * s.w + bv.w, 0.f);
    if (layer == 0) {
        float4 db = *(const float4*)&g_db2[t];
        h.x *= db.x; h.y *= db.y; h.z *= db.z; h.w *= db.w;
        ((float4*)g_z2)[i4] = h;
    } else {
        ((float4*)g_h2)[i4] = h;
    }
}

// ---------------- logits: out[b][c] = h2[b, :512] . W[c] + bl[c] ----------------
__global__ void logits_kernel(const float* __restrict__ W, const float* __restrict__ bl,
                              float* __restrict__ out) {
    int b = blockIdx.x;
    int cls = threadIdx.x >> 5;
    int lane = threadIdx.x & 31;
    float s = 0.f;
#pragma unroll
    for (int m = 0; m < 16; m++) {
        int j = lane + 32 * m;
        s = fmaf(g_h2[b * LSZ + j], W[cls * FCN + j], s);
    }
#pragma unroll
    for (int off = 16; off; off >>= 1) s += __shfl_down_sync(0xffffffffu, s, off);
    if (lane == 0) out[b * NCLS + cls] = s + bl[cls];
}

// ---------------- launch ----------------
extern "C" void kernel_launch(void* const* d_in, const int* in_sizes, int n_in,
                              void* d_out, int out_size) {
    const float* x    = (const float*)d_in[0];
    const float* G1   = (const float*)d_in[1];
    const float* H1   = (const float*)d_in[2];
    const float* sdA1 = (const float*)d_in[3];
    const float* sdB1 = (const float*)d_in[4];
    const float* b1   = (const float*)d_in[5];
    const float* G2   = (const float*)d_in[6];
    const float* H2   = (const float*)d_in[7];
    const float* sdA2 = (const float*)d_in[8];
    const float* sdB2 = (const float*)d_in[9];
    const float* b2   = (const float*)d_in[10];
    const float* W    = (const float*)d_in[11];
    const float* bl   = (const float*)d_in[12];
    float* out = (float*)d_out;

    const int QSM1 = (R1 * 128 + R1 * 260 + 16 * 128) * 4;  // 82688
    const int QSM2 = (R2 * 128 + R2 * 260 + 16 * 128) * 4;  // 33024
    const int GSM  = (128 * 132 + 64 * 132) * 4;            // 101376

    cudaFuncSetAttribute(qrot_kernel<R1>, cudaFuncAttributeMaxDynamicSharedMemorySize, QSM1);
    cudaFuncSetAttribute(qrot_kernel<R2>, cudaFuncAttributeMaxDynamicSharedMemorySize, QSM2);
    cudaFuncSetAttribute(skewgemm_kernel, cudaFuncAttributeMaxDynamicSharedMemorySize, GSM);

    scan_kernel<<<4, 1024>>>(sdA1, sdB1, sdA2, sdB2);
    prep_kernel<<<1024, 256>>>(G1, H1, G2, H2, x);

    // layer 1
    qrot_kernel<R1><<<dim3(32, 32), 256, QSM1>>>();
    cumsum_kernel<<<dim3(16, 32), 256>>>();
    skewgemm_kernel<<<dim3(32, 8), 256, GSM>>>(0);
    epilogue_kernel<<<256, 256>>>(b1, 0);

    // layer 2
    qrot_kernel<R2><<<dim3(32, 32), 256, QSM2>>>();
    cumsum_kernel<<<dim3(16, 32), 256>>>();
    skewgemm_kernel<<<dim3(32, 8), 256, GSM>>>(1);
    epilogue_kernel<<<256, 256>>>(b2, 1);

    logits_kernel<<<64, 320>>>(W, bl, out);
}

// round 6
// speedup vs baseline: 2.3379x; 2.3379x over previous
#include <cuda_runtime.h>

#define LSZ   4096
#define BATCH 64
#define R1    48
#define R2    16
#define NIN   1024
#define FCN   512
#define NCLS  10
#define DMAXS 5120   // stride for diagonal-total arrays

// ---------------- scratch (device globals; no allocation allowed) ----------------
__device__ float g_da1[LSZ], g_db1[LSZ], g_da2[LSZ], g_db2[LSZ];
__device__ float g_Gt1[R1*LSZ], g_Ht1[R1*LSZ];
__device__ float g_Gt2[R2*LSZ], g_Ht2[R2*LSZ];
__device__ float g_M[(size_t)LSZ*1024];     // 16MB strip (Q then M, in place); layer2 uses 512*4096
__device__ float g_tot[32*DMAXS];
__device__ float g_z1[BATCH*NIN];       // layer-1 input, compact 64x1024
__device__ float g_z2[BATCH*LSZ];       // layer-2 input, 64x4096
__device__ float g_h2[BATCH*FCN];       // layer-2 output, compact 64x512
__device__ float g_Ypart[8*BATCH*LSZ];  // split-K partials (max 2M floats)

// ---------------- cumprod scan: d[0]=1, d[j]=prod_{k<j} subd[k] ----------------
__global__ void scan_kernel(const float* __restrict__ sA1, const float* __restrict__ sB1,
                            const float* __restrict__ sA2, const float* __restrict__ sB2) {
    const float* src; float* dst;
    if      (blockIdx.x == 0) { src = sA1; dst = g_da1; }
    else if (blockIdx.x == 1) { src = sB1; dst = g_db1; }
    else if (blockIdx.x == 2) { src = sA2; dst = g_da2; }
    else                      { src = sB2; dst = g_db2; }

    __shared__ float part[1024];
    int tid = threadIdx.x;
    float v[4]; float p = 1.f;
#pragma unroll
    for (int j = 0; j < 4; j++) {
        int idx = tid * 4 + j;
        float s = (idx < LSZ - 1) ? src[idx] : 1.f;
        p *= s; v[j] = p;
    }
    part[tid] = p; __syncthreads();
    for (int off = 1; off < 1024; off <<= 1) {
        float x = part[tid];
        float m = (tid >= off) ? part[tid - off] : 1.f;
        __syncthreads();
        part[tid] = x * m;
        __syncthreads();
    }
    float excl = (tid == 0) ? 1.f : part[tid - 1];
    if (tid == 0) dst[0] = 1.f;
#pragma unroll
    for (int j = 0; j < 4; j++) {
        int idx = tid * 4 + j;
        if (idx < LSZ - 1) dst[idx + 1] = excl * v[j];
    }
}

// ---------------- prep: Gt=G/da, Ht=H/db, z1 = db1 * x (compact 1024) ----------------
__global__ void prep_kernel(const float* __restrict__ G1, const float* __restrict__ H1,
                            const float* __restrict__ G2, const float* __restrict__ H2,
                            const float* __restrict__ x) {
    int tid = blockIdx.x * blockDim.x + threadIdx.x;
    int j = tid & (LSZ - 1);
    if (tid < R1 * LSZ) {
        g_Gt1[tid] = G1[tid] / g_da1[j];
        g_Ht1[tid] = H1[tid] / g_db1[j];
    }
    if (tid < R2 * LSZ) {
        g_Gt2[tid] = G2[tid] / g_da2[j];
        g_Ht2[tid] = H2[tid] / g_db2[j];
    }
    if (tid < BATCH * NIN) {
        int jj = tid & (NIN - 1);
        g_z1[tid] = x[tid] * g_db1[jj];
    }
}

// ---------------- Q = Gt^T Ht (standard layout strip) ----------------
// Q[t][w] = sum_i Gt[i][t0+..] * Ht[i][w0+..]; 128x128 tile, 256 thr, 8x8 micro (4+4 split)
template <int R>
__global__ __launch_bounds__(256, 2) void qgemm_kernel(const float* __restrict__ Gt,
                                                       const float* __restrict__ Ht,
                                                       float* __restrict__ Q, int ld) {
    extern __shared__ float sh[];
    float* sG = sh;             // R x 132
    float* sH = sh + R * 132;   // R x 132
    int t0 = blockIdx.y << 7, w0 = blockIdx.x << 7;
    for (int idx = threadIdx.x; idx < R * 128; idx += 256) {
        int i = idx >> 7, e = idx & 127;
        sG[i * 132 + e] = Gt[i * LSZ + t0 + e];
        sH[i * 132 + e] = Ht[i * LSZ + w0 + e];
    }
    __syncthreads();

    int tx = threadIdx.x & 15, ty = threadIdx.x >> 4;
    float acc[8][8];
#pragma unroll
    for (int u = 0; u < 8; u++)
#pragma unroll
        for (int v = 0; v < 8; v++) acc[u][v] = 0.f;

    for (int i = 0; i < R; i++) {
        float a[8], b[8];
        ((float4*)a)[0] = *(const float4*)&sG[i * 132 + ty * 4];
        ((float4*)a)[1] = *(const float4*)&sG[i * 132 + 64 + ty * 4];
        ((float4*)b)[0] = *(const float4*)&sH[i * 132 + tx * 4];
        ((float4*)b)[1] = *(const float4*)&sH[i * 132 + 64 + tx * 4];
#pragma unroll
        for (int u = 0; u < 8; u++)
#pragma unroll
            for (int v = 0; v < 8; v++) acc[u][v] = fmaf(a[u], b[v], acc[u][v]);
    }
#pragma unroll
    for (int u = 0; u < 8; u++) {
        int t = t0 + (u < 4 ? ty * 4 + u : 64 + ty * 4 + u - 4);
        *(float4*)&Q[(size_t)t * ld + w0 + tx * 4]      = make_float4(acc[u][0], acc[u][1], acc[u][2], acc[u][3]);
        *(float4*)&Q[(size_t)t * ld + w0 + 64 + tx * 4] = make_float4(acc[u][4], acc[u][5], acc[u][6], acc[u][7]);
    }
}

// ---------------- per-tile diagonal totals: tot[k][d] = sum_{t in tile, 0<=t-d<ld} Q[t][t-d] ----
__global__ void tot_kernel(const float* __restrict__ Q, int ld) {
    int k = blockIdx.x;
    int t0 = k << 7;
    int d = t0 - (ld - 1) + (blockIdx.y << 7) + threadIdx.x;
    int dIdx = d + (ld - 1);
    float acc = 0.f;
#pragma unroll 4
    for (int r = 0; r < 128; r++) {
        int t = t0 + r;
        int w = t - d;
        if (w >= 0 && w < ld) acc += Q[(size_t)t * ld + w];
    }
    g_tot[k * DMAXS + dIdx] = acc;
}

// ---------------- segmented diagonal cumsum, in place ----------------
// prefix only over tiles the diagonal actually intersects (k2 >= d>>7 for d>0):
// every g_tot slot read is written by THIS layer's tot_kernel in the same iteration.
__global__ void cumsum_kernel(float* __restrict__ Q, int ld) {
    int k = blockIdx.x;
    int t0 = k << 7;
    int d = t0 - (ld - 1) + (blockIdx.y << 7) + threadIdx.x;
    int dIdx = d + (ld - 1);
    int k2min = (d > 0) ? (d >> 7) : 0;
    float acc = 0.f;
    for (int k2 = k2min; k2 < k; k2++) acc += g_tot[k2 * DMAXS + dIdx];
#pragma unroll 4
    for (int r = 0; r < 128; r++) {
        int t = t0 + r;
        int w = t - d;
        if (w >= 0 && w < ld) {
            size_t a = (size_t)t * ld + w;
            acc += Q[a];
            Q[a] = acc;
        }
    }
}

// ---------------- main GEMM: Ypart[slice][b][t] = sum_{w in slice(128)} M[t][w] z[b][w] -------
// 128t x 64b tile, one 128-wide K slice per block. micro: t=tx+16u (8), b=ty+16v (4).
// smem pad = 132 floats (16B-aligned rows for float4 stores).
__global__ __launch_bounds__(256, 2) void skewgemm_kernel(const float* __restrict__ M, int ld,
                                                          const float* __restrict__ z, int zld,
                                                          float* __restrict__ Ypart, int Tdim) {
    extern __shared__ float sh[];
    float* sM = sh;                 // 128 x 132
    float* sz = sh + 128 * 132;     // 64 x 132
    int t0 = blockIdx.x << 7;
    int w0 = blockIdx.y << 7;
    int tx = threadIdx.x & 15, ty = threadIdx.x >> 4;
    float acc[8][4];
#pragma unroll
    for (int u = 0; u < 8; u++)
#pragma unroll
        for (int v = 0; v < 4; v++) acc[u][v] = 0.f;

    for (int idx = threadIdx.x; idx < 128 * 32; idx += 256) {
        int row = idx >> 5, c4 = idx & 31;
        float4 m4 = *(const float4*)&M[(size_t)(t0 + row) * ld + w0 + 4 * c4];
        *(float4*)&sM[row * 132 + 4 * c4] = m4;
    }
    for (int idx = threadIdx.x; idx < 64 * 32; idx += 256) {
        int b = idx >> 5, c4 = idx & 31;
        float4 z4 = *(const float4*)&z[(size_t)b * zld + w0 + 4 * c4];
        *(float4*)&sz[b * 132 + 4 * c4] = z4;
    }
    __syncthreads();
#pragma unroll 4
    for (int ww = 0; ww < 128; ww++) {
        float a[8], zb[4];
#pragma unroll
        for (int u = 0; u < 8; u++) a[u] = sM[(tx + 16 * u) * 132 + ww];
#pragma unroll
        for (int v = 0; v < 4; v++) zb[v] = sz[(ty + 16 * v) * 132 + ww];
#pragma unroll
        for (int u = 0; u < 8; u++)
#pragma unroll
            for (int v = 0; v < 4; v++) acc[u][v] = fmaf(a[u], zb[v], acc[u][v]);
    }
#pragma unroll
    for (int u = 0; u < 8; u++) {
        int t = t0 + tx + 16 * u;
#pragma unroll
        for (int v = 0; v < 4; v++) {
            int b = ty + 16 * v;
            Ypart[((size_t)blockIdx.y * BATCH + b) * Tdim + t] = acc[u][v];
        }
    }
}

// ---------------- epilogue 1: reduce 8 partials, z2 = relu(da1*s + b1) * db2 (full 4096) -------
__global__ void epilogue1_kernel(const float* __restrict__ bias) {
    int i4 = blockIdx.x * 256 + threadIdx.x;
    if (i4 >= BATCH * LSZ / 4) return;
    const float4* Yp = (const float4*)g_Ypart;
    float4 s = Yp[i4];
#pragma unroll
    for (int k = 1; k < 8; k++) {
        float4 p = Yp[(size_t)k * (BATCH * LSZ / 4) + i4];
        s.x += p.x; s.y += p.y; s.z += p.z; s.w += p.w;
    }
    int t = (i4 * 4) & (LSZ - 1);
    float4 dav = *(const float4*)&g_da1[t];
    float4 bv  = *(const float4*)&bias[t];
    float4 db  = *(const float4*)&g_db2[t];
    float4 h;
    h.x = fmaxf(dav.x * s.x + bv.x, 0.f) * db.x;
    h.y = fmaxf(dav.y * s.y + bv.y, 0.f) * db.y;
    h.z = fmaxf(dav.z * s.z + bv.z, 0.f) * db.z;
    h.w = fmaxf(dav.w * s.w + bv.w, 0.f) * db.w;
    ((float4*)g_z2)[i4] = h;
}

// ---------------- epilogue 2: reduce 32 partials over 64x512, h2 = relu(da2*s + b2) -----------
__global__ void epilogue2_kernel(const float* __restrict__ bias) {
    int i4 = blockIdx.x * 256 + threadIdx.x;
    if (i4 >= BATCH * FCN / 4) return;
    const float4* Yp = (const float4*)g_Ypart;
    float4 s = Yp[i4];
#pragma unroll
    for (int k = 1; k < 32; k++) {
        float4 p = Yp[(size_t)k * (BATCH * FCN / 4) + i4];
        s.x += p.x; s.y += p.y; s.z += p.z; s.w += p.w;
    }
    int t = (i4 * 4) & (FCN - 1);
    float4 dav = *(const float4*)&g_da2[t];
    float4 bv  = *(const float4*)&bias[t];
    float4 h;
    h.x = fmaxf(dav.x * s.x + bv.x, 0.f);
    h.y = fmaxf(dav.y * s.y + bv.y, 0.f);
    h.z = fmaxf(dav.z * s.z + bv.z, 0.f);
    h.w = fmaxf(dav.w * s.w + bv.w, 0.f);
    ((float4*)g_h2)[i4] = h;
}

// ---------------- logits: out[b][c] = h2[b] . W[c] + bl[c] ----------------
__global__ void logits_kernel(const float* __restrict__ W, const float* __restrict__ bl,
                              float* __restrict__ out) {
    int b = blockIdx.x;
    int cls = threadIdx.x >> 5;
    int lane = threadIdx.x & 31;
    float s = 0.f;
#pragma unroll
    for (int m = 0; m < 16; m++) {
        int j = lane + 32 * m;
        s = fmaf(g_h2[b * FCN + j], W[cls * FCN + j], s);
    }
#pragma unroll
    for (int off = 16; off; off >>= 1) s += __shfl_down_sync(0xffffffffu, s, off);
    if (lane == 0) out[b * NCLS + cls] = s + bl[cls];
}

// ---------------- launch ----------------
extern "C" void kernel_launch(void* const* d_in, const int* in_sizes, int n_in,
                              void* d_out, int out_size) {
    const float* x    = (const float*)d_in[0];
    const float* G1   = (const float*)d_in[1];
    const float* H1   = (const float*)d_in[2];
    const float* sdA1 = (const float*)d_in[3];
    const float* sdB1 = (const float*)d_in[4];
    const float* b1   = (const float*)d_in[5];
    const float* G2   = (const float*)d_in[6];
    const float* H2   = (const float*)d_in[7];
    const float* sdA2 = (const float*)d_in[8];
    const float* sdB2 = (const float*)d_in[9];
    const float* b2   = (const float*)d_in[10];
    const float* W    = (const float*)d_in[11];
    const float* bl   = (const float*)d_in[12];
    float* out = (float*)d_out;

    const int QSM1 = R1 * 132 * 2 * 4;           // 50688
    const int QSM2 = R2 * 132 * 2 * 4;           // 16896
    const int GSM  = (128 * 132 + 64 * 132) * 4; // 101376

    cudaFuncSetAttribute(qgemm_kernel<R1>, cudaFuncAttributeMaxDynamicSharedMemorySize, QSM1);
    cudaFuncSetAttribute(qgemm_kernel<R2>, cudaFuncAttributeMaxDynamicSharedMemorySize, QSM2);
    cudaFuncSetAttribute(skewgemm_kernel, cudaFuncAttributeMaxDynamicSharedMemorySize, GSM);

    float* Mbuf;  cudaGetSymbolAddress((void**)&Mbuf, g_M);
    float* Ypart; cudaGetSymbolAddress((void**)&Ypart, g_Ypart);
    float* z1;    cudaGetSymbolAddress((void**)&z1, g_z1);
    float* z2;    cudaGetSymbolAddress((void**)&z2, g_z2);
    float* Gt1;   cudaGetSymbolAddress((void**)&Gt1, g_Gt1);
    float* Ht1;   cudaGetSymbolAddress((void**)&Ht1, g_Ht1);
    float* Gt2;   cudaGetSymbolAddress((void**)&Gt2, g_Gt2);
    float* Ht2;   cudaGetSymbolAddress((void**)&Ht2, g_Ht2);

    scan_kernel<<<4, 1024>>>(sdA1, sdB1, sdA2, sdB2);
    prep_kernel<<<1024, 256>>>(G1, H1, G2, H2, x);

    // ---- layer 1: strip 4096 x 1024 (input zero-padded beyond 1024) ----
    qgemm_kernel<R1><<<dim3(8, 32), 256, QSM1>>>(Gt1, Ht1, Mbuf, 1024);
    tot_kernel<<<dim3(32, 9), 128>>>(Mbuf, 1024);
    cumsum_kernel<<<dim3(32, 9), 128>>>(Mbuf, 1024);
    skewgemm_kernel<<<dim3(32, 8), 256, GSM>>>(Mbuf, 1024, z1, 1024, Ypart, LSZ);
    epilogue1_kernel<<<256, 256>>>(b1);

    // ---- layer 2: strip 512 x 4096 (only first 512 outputs used) ----
    qgemm_kernel<R2><<<dim3(32, 4), 256, QSM2>>>(Gt2, Ht2, Mbuf, 4096);
    tot_kernel<<<dim3(4, 33), 128>>>(Mbuf, 4096);
    cumsum_kernel<<<dim3(4, 33), 128>>>(Mbuf, 4096);
    skewgemm_kernel<<<dim3(4, 32), 256, GSM>>>(Mbuf, 4096, z2, 4096, Ypart, FCN);
    epilogue2_kernel<<<32, 256>>>(b2);

    logits_kernel<<<64, 320>>>(W, bl, out);
}

// round 7
// speedup vs baseline: 3.1907x; 1.3647x over previous
#include <cuda_runtime.h>

#define LSZ   4096
#define BATCH 64
#define R1    48
#define R2    16
#define NIN   1024
#define FCN   512
#define NCLS  10
#define DMAXS 5120   // stride for diagonal-total arrays (global dIdx)

// ---------------- scratch (device globals; no allocation allowed) ----------------
__device__ float g_da1[LSZ], g_db1[LSZ], g_da2[LSZ], g_db2[LSZ];
__device__ float g_ida1[LSZ], g_idb1[LSZ], g_ida2[LSZ], g_idb2[LSZ];
__device__ float g_Gt1[R1*LSZ], g_Ht1[R1*LSZ];
__device__ float g_Gt2[R2*LSZ], g_Ht2[R2*LSZ];
__device__ float g_M[(size_t)LSZ*1024];     // 16MB strip (Q then M, in place); layer2 uses 512*4096
__device__ float g_tot[64*DMAXS];           // 64-row-tile diagonal totals
__device__ float g_z1[BATCH*NIN];       // layer-1 input, compact 64x1024
__device__ float g_z2[BATCH*LSZ];       // layer-2 input, 64x4096
__device__ float g_h2[BATCH*FCN];       // layer-2 output, compact 64x512
__device__ float g_Ypart[32*BATCH*FCN > 4*BATCH*LSZ ? 32*BATCH*FCN : 4*BATCH*LSZ]; // split-K partials

// ---------------- cumprod scan: d[0]=1, d[j]=prod_{k<j} subd[k]; also reciprocals ------------
__global__ void scan_kernel(const float* __restrict__ sA1, const float* __restrict__ sB1,
                            const float* __restrict__ sA2, const float* __restrict__ sB2) {
    const float* src; float* dst; float* inv;
    if      (blockIdx.x == 0) { src = sA1; dst = g_da1; inv = g_ida1; }
    else if (blockIdx.x == 1) { src = sB1; dst = g_db1; inv = g_idb1; }
    else if (blockIdx.x == 2) { src = sA2; dst = g_da2; inv = g_ida2; }
    else                      { src = sB2; dst = g_db2; inv = g_idb2; }

    __shared__ float part[1024];
    int tid = threadIdx.x;
    float v[4]; float p = 1.f;
#pragma unroll
    for (int j = 0; j < 4; j++) {
        int idx = tid * 4 + j;
        float s = (idx < LSZ - 1) ? src[idx] : 1.f;
        p *= s; v[j] = p;
    }
    part[tid] = p; __syncthreads();
    for (int off = 1; off < 1024; off <<= 1) {
        float x = part[tid];
        float m = (tid >= off) ? part[tid - off] : 1.f;
        __syncthreads();
        part[tid] = x * m;
        __syncthreads();
    }
    float excl = (tid == 0) ? 1.f : part[tid - 1];
    if (tid == 0) { dst[0] = 1.f; inv[0] = 1.f; }
#pragma unroll
    for (int j = 0; j < 4; j++) {
        int idx = tid * 4 + j;
        if (idx < LSZ - 1) {
            float val = excl * v[j];
            dst[idx + 1] = val;
            inv[idx + 1] = 1.0f / val;
        }
    }
}

// ---------------- prep: Gt=G*ida, Ht=H*idb, z1 = db1 * x (compact 1024) ----------------
__global__ void prep_kernel(const float* __restrict__ G1, const float* __restrict__ H1,
                            const float* __restrict__ G2, const float* __restrict__ H2,
                            const float* __restrict__ x) {
    int tid = blockIdx.x * blockDim.x + threadIdx.x;
    int j = tid & (LSZ - 1);
    if (tid < R1 * LSZ) {
        g_Gt1[tid] = G1[tid] * g_ida1[j];
        g_Ht1[tid] = H1[tid] * g_idb1[j];
    }
    if (tid < R2 * LSZ) {
        g_Gt2[tid] = G2[tid] * g_ida2[j];
        g_Ht2[tid] = H2[tid] * g_idb2[j];
    }
    if (tid < BATCH * NIN) {
        int jj = tid & (NIN - 1);
        g_z1[tid] = x[tid] * g_db1[jj];
    }
}

// ---------------- Q = Gt^T Ht (standard layout strip) ----------------
// Q[t][w] = sum_i Gt[i][t0+..] * Ht[i][w0+..]; 128x128 tile, 256 thr, 8x8 micro (4+4 split)
template <int R>
__global__ __launch_bounds__(256, 2) void qgemm_kernel(const float* __restrict__ Gt,
                                                       const float* __restrict__ Ht,
                                                       float* __restrict__ Q, int ld) {
    extern __shared__ float sh[];
    float* sG = sh;             // R x 132
    float* sH = sh + R * 132;   // R x 132
    int t0 = blockIdx.y << 7, w0 = blockIdx.x << 7;
    for (int idx = threadIdx.x; idx < R * 128; idx += 256) {
        int i = idx >> 7, e = idx & 127;
        sG[i * 132 + e] = Gt[i * LSZ + t0 + e];
        sH[i * 132 + e] = Ht[i * LSZ + w0 + e];
    }
    __syncthreads();

    int tx = threadIdx.x & 15, ty = threadIdx.x >> 4;
    float acc[8][8];
#pragma unroll
    for (int u = 0; u < 8; u++)
#pragma unroll
        for (int v = 0; v < 8; v++) acc[u][v] = 0.f;

    for (int i = 0; i < R; i++) {
        float a[8], b[8];
        ((float4*)a)[0] = *(const float4*)&sG[i * 132 + ty * 4];
        ((float4*)a)[1] = *(const float4*)&sG[i * 132 + 64 + ty * 4];
        ((float4*)b)[0] = *(const float4*)&sH[i * 132 + tx * 4];
        ((float4*)b)[1] = *(const float4*)&sH[i * 132 + 64 + tx * 4];
#pragma unroll
        for (int u = 0; u < 8; u++)
#pragma unroll
            for (int v = 0; v < 8; v++) acc[u][v] = fmaf(a[u], b[v], acc[u][v]);
    }
#pragma unroll
    for (int u = 0; u < 8; u++) {
        int t = t0 + (u < 4 ? ty * 4 + u : 64 + ty * 4 + u - 4);
        *(float4*)&Q[(size_t)t * ld + w0 + tx * 4]      = make_float4(acc[u][0], acc[u][1], acc[u][2], acc[u][3]);
        *(float4*)&Q[(size_t)t * ld + w0 + 64 + tx * 4] = make_float4(acc[u][4], acc[u][5], acc[u][6], acc[u][7]);
    }
}

// ---------------- per-64-row-tile diagonal totals, clamped branch-free loop ----------------
// tot[k][dIdx] = sum_{r in [rlo,rhi)} Q[(t0+r)][t0+r-d],  d = dIdx-(ld-1)
__global__ void tot_kernel(const float* __restrict__ Q, int ld) {
    int k = blockIdx.x;
    int t0 = k << 6;
    int off = (blockIdx.y << 8) + threadIdx.x;
    if (off >= ld + 63) return;
    int dIdx = t0 + off;                 // global diagonal index
    int d = dIdx - (ld - 1);
    int rlo = d - t0; rlo = rlo > 0 ? rlo : 0;
    int rhi = d - t0 + ld; rhi = rhi < 64 ? rhi : 64;
    float acc = 0.f;
    const float* p = &Q[(size_t)(t0 + rlo) * ld + (t0 + rlo - d)];
#pragma unroll 4
    for (int r = rlo; r < rhi; r++) {
        acc += *p;
        p += ld + 1;
    }
    g_tot[k * DMAXS + dIdx] = acc;
}

// ---------------- segmented diagonal cumsum, in place, clamped + prefetched prefix ------------
__global__ void cumsum_kernel(float* __restrict__ Q, int ld) {
    int k = blockIdx.x;
    int t0 = k << 6;
    int off = (blockIdx.y << 8) + threadIdx.x;
    if (off >= ld + 63) return;
    int dIdx = t0 + off;
    int d = dIdx - (ld - 1);
    int k2min = (d > 0) ? (d >> 6) : 0;
    float acc = 0.f;
#pragma unroll 4
    for (int k2 = k2min; k2 < k; k2++) acc += g_tot[k2 * DMAXS + dIdx];
    int rlo = d - t0; rlo = rlo > 0 ? rlo : 0;
    int rhi = d - t0 + ld; rhi = rhi < 64 ? rhi : 64;
    float* p = &Q[(size_t)(t0 + rlo) * ld + (t0 + rlo - d)];
#pragma unroll 4
    for (int r = rlo; r < rhi; r++) {
        acc += *p;
        *p = acc;
        p += ld + 1;
    }
}

// ---------------- main GEMM: Ypart[slice][b][t] = sum_{w in slice} M[t][w] z[b][w] -----------
// 128t x 64b tile, nchunk 128-wide K chunks per slice. micro: t=tx+16u (8), b=ty+16v (4).
__global__ __launch_bounds__(256, 2) void skewgemm_kernel(const float* __restrict__ M, int ld,
                                                          const float* __restrict__ z, int zld,
                                                          float* __restrict__ Ypart, int Tdim,
                                                          int nchunk) {
    extern __shared__ float sh[];
    float* sM = sh;                 // 128 x 132
    float* sz = sh + 128 * 132;     // 64 x 132
    int t0 = blockIdx.x << 7;
    int w0b = blockIdx.y * nchunk * 128;
    int tx = threadIdx.x & 15, ty = threadIdx.x >> 4;
    float acc[8][4];
#pragma unroll
    for (int u = 0; u < 8; u++)
#pragma unroll
        for (int v = 0; v < 4; v++) acc[u][v] = 0.f;

    for (int c = 0; c < nchunk; c++) {
        int w0 = w0b + c * 128;
        for (int idx = threadIdx.x; idx < 128 * 32; idx += 256) {
            int row = idx >> 5, c4 = idx & 31;
            float4 m4 = *(const float4*)&M[(size_t)(t0 + row) * ld + w0 + 4 * c4];
            *(float4*)&sM[row * 132 + 4 * c4] = m4;
        }
        for (int idx = threadIdx.x; idx < 64 * 32; idx += 256) {
            int b = idx >> 5, c4 = idx & 31;
            float4 z4 = *(const float4*)&z[(size_t)b * zld + w0 + 4 * c4];
            *(float4*)&sz[b * 132 + 4 * c4] = z4;
        }
        __syncthreads();
#pragma unroll 4
        for (int ww = 0; ww < 128; ww++) {
            float a[8], zb[4];
#pragma unroll
            for (int u = 0; u < 8; u++) a[u] = sM[(tx + 16 * u) * 132 + ww];
#pragma unroll
            for (int v = 0; v < 4; v++) zb[v] = sz[(ty + 16 * v) * 132 + ww];
#pragma unroll
            for (int u = 0; u < 8; u++)
#pragma unroll
                for (int v = 0; v < 4; v++) acc[u][v] = fmaf(a[u], zb[v], acc[u][v]);
        }
        __syncthreads();
    }
#pragma unroll
    for (int u = 0; u < 8; u++) {
        int t = t0 + tx + 16 * u;
#pragma unroll
        for (int v = 0; v < 4; v++) {
            int b = ty + 16 * v;
            Ypart[((size_t)blockIdx.y * BATCH + b) * Tdim + t] = acc[u][v];
        }
    }
}

// ---------------- epilogue 1: reduce 4 partials, z2 = relu(da1*s + b1) * db2 (full 4096) -------
__global__ void epilogue1_kernel(const float* __restrict__ bias) {
    int i4 = blockIdx.x * 256 + threadIdx.x;
    if (i4 >= BATCH * LSZ / 4) return;
    const float4* Yp = (const float4*)g_Ypart;
    float4 s = Yp[i4];
#pragma unroll
    for (int k = 1; k < 4; k++) {
        float4 p = Yp[(size_t)k * (BATCH * LSZ / 4) + i4];
        s.x += p.x; s.y += p.y; s.z += p.z; s.w += p.w;
    }
    int t = (i4 * 4) & (LSZ - 1);
    float4 dav = *(const float4*)&g_da1[t];
    float4 bv  = *(const float4*)&bias[t];
    float4 db  = *(const float4*)&g_db2[t];
    float4 h;
    h.x = fmaxf(dav.x * s.x + bv.x, 0.f) * db.x;
    h.y = fmaxf(dav.y * s.y + bv.y, 0.f) * db.y;
    h.z = fmaxf(dav.z * s.z + bv.z, 0.f) * db.z;
    h.w = fmaxf(dav.w * s.w + bv.w, 0.f) * db.w;
    ((float4*)g_z2)[i4] = h;
}

// ---------------- epilogue 2: reduce 32 partials over 64x512, h2 = relu(da2*s + b2) -----------
__global__ void epilogue2_kernel(const float* __restrict__ bias) {
    int i4 = blockIdx.x * 256 + threadIdx.x;
    if (i4 >= BATCH * FCN / 4) return;
    const float4* Yp = (const float4*)g_Ypart;
    float4 s = Yp[i4];
#pragma unroll
    for (int k = 1; k < 32; k++) {
        float4 p = Yp[(size_t)k * (BATCH * FCN / 4) + i4];
        s.x += p.x; s.y += p.y; s.z += p.z; s.w += p.w;
    }
    int t = (i4 * 4) & (FCN - 1);
    float4 dav = *(const float4*)&g_da2[t];
    float4 bv  = *(const float4*)&bias[t];
    float4 h;
    h.x = fmaxf(dav.x * s.x + bv.x, 0.f);
    h.y = fmaxf(dav.y * s.y + bv.y, 0.f);
    h.z = fmaxf(dav.z * s.z + bv.z, 0.f);
    h.w = fmaxf(dav.w * s.w + bv.w, 0.f);
    ((float4*)g_h2)[i4] = h;
}

// ---------------- logits: out[b][c] = h2[b] . W[c] + bl[c] ----------------
__global__ void logits_kernel(const float* __restrict__ W, const float* __restrict__ bl,
                              float* __restrict__ out) {
    int b = blockIdx.x;
    int cls = threadIdx.x >> 5;
    int lane = threadIdx.x & 31;
    float s = 0.f;
#pragma unroll
    for (int m = 0; m < 16; m++) {
        int j = lane + 32 * m;
        s = fmaf(g_h2[b * FCN + j], W[cls * FCN + j], s);
    }
#pragma unroll
    for (int off = 16; off; off >>= 1) s += __shfl_down_sync(0xffffffffu, s, off);
    if (lane == 0) out[b * NCLS + cls] = s + bl[cls];
}

// ---------------- launch ----------------
extern "C" void kernel_launch(void* const* d_in, const int* in_sizes, int n_in,
                              void* d_out, int out_size) {
    const float* x    = (const float*)d_in[0];
    const float* G1   = (const float*)d_in[1];
    const float* H1   = (const float*)d_in[2];
    const float* sdA1 = (const float*)d_in[3];
    const float* sdB1 = (const float*)d_in[4];
    const float* b1   = (const float*)d_in[5];
    const float* G2   = (const float*)d_in[6];
    const float* H2   = (const float*)d_in[7];
    const float* sdA2 = (const float*)d_in[8];
    const float* sdB2 = (const float*)d_in[9];
    const float* b2   = (const float*)d_in[10];
    const float* W    = (const float*)d_in[11];
    const float* bl   = (const float*)d_in[12];
    float* out = (float*)d_out;

    const int QSM1 = R1 * 132 * 2 * 4;           // 50688
    const int QSM2 = R2 * 132 * 2 * 4;           // 16896
    const int GSM  = (128 * 132 + 64 * 132) * 4; // 101376

    cudaFuncSetAttribute(qgemm_kernel<R1>, cudaFuncAttributeMaxDynamicSharedMemorySize, QSM1);
    cudaFuncSetAttribute(qgemm_kernel<R2>, cudaFuncAttributeMaxDynamicSharedMemorySize, QSM2);
    cudaFuncSetAttribute(skewgemm_kernel, cudaFuncAttributeMaxDynamicSharedMemorySize, GSM);

    float* Mbuf;  cudaGetSymbolAddress((void**)&Mbuf, g_M);
    float* Ypart; cudaGetSymbolAddress((void**)&Ypart, g_Ypart);
    float* z1;    cudaGetSymbolAddress((void**)&z1, g_z1);
    float* z2;    cudaGetSymbolAddress((void**)&z2, g_z2);
    float* Gt1;   cudaGetSymbolAddress((void**)&Gt1, g_Gt1);
    float* Ht1;   cudaGetSymbolAddress((void**)&Ht1, g_Ht1);
    float* Gt2;   cudaGetSymbolAddress((void**)&Gt2, g_Gt2);
    float* Ht2;   cudaGetSymbolAddress((void**)&Ht2, g_Ht2);

    scan_kernel<<<4, 1024>>>(sdA1, sdB1, sdA2, sdB2);
    prep_kernel<<<1024, 256>>>(G1, H1, G2, H2, x);

    // ---- layer 1: strip 4096 x 1024 (input zero-padded beyond 1024) ----
    qgemm_kernel<R1><<<dim3(8, 32), 256, QSM1>>>(Gt1, Ht1, Mbuf, 1024);
    tot_kernel<<<dim3(64, 5), 256>>>(Mbuf, 1024);        // 64-row tiles, span 1087
    cumsum_kernel<<<dim3(64, 5), 256>>>(Mbuf, 1024);
    skewgemm_kernel<<<dim3(32, 4), 256, GSM>>>(Mbuf, 1024, z1, 1024, Ypart, LSZ, 2);
    epilogue1_kernel<<<256, 256>>>(b1);

    // ---- layer 2: strip 512 x 4096 (only first 512 outputs used) ----
    qgemm_kernel<R2><<<dim3(32, 4), 256, QSM2>>>(Gt2, Ht2, Mbuf, 4096);
    tot_kernel<<<dim3(8, 17), 256>>>(Mbuf, 4096);        // span 4159
    cumsum_kernel<<<dim3(8, 17), 256>>>(Mbuf, 4096);
    skewgemm_kernel<<<dim3(4, 32), 256, GSM>>>(Mbuf, 4096, z2, 4096, Ypart, FCN, 1);
    epilogue2_kernel<<<32, 256>>>(b2);

    logits_kernel<<<64, 320>>>(W, bl, out);
}

// round 8
// speedup vs baseline: 4.5924x; 1.4393x over previous
#include <cuda_runtime.h>

#define LSZ   4096
#define BATCH 64
#define R1    48
#define R2    16
#define NIN   1024
#define FCN   512
#define NCLS  10

// ---------------- scratch (device globals; no allocation allowed) ----------------
__device__ float g_da1[LSZ], g_db1[LSZ], g_da2[LSZ], g_db2[LSZ];
__device__ float g_ida1[LSZ], g_idb1[LSZ], g_ida2[LSZ], g_idb2[LSZ];
__device__ float g_Gt1[R1*LSZ], g_Ht1[R1*LSZ];
__device__ float g_Gt2[R2*LSZ], g_Ht2[R2*LSZ];
__device__ float g_M[(size_t)LSZ*1024];     // 16MB Q strip; layer2 uses 512*4096 = 8MB
__device__ float g_sub[256*256];            // per-subtile diagonal totals (max 32*8 subtiles)
__device__ float g_pref[256*256];           // per-subtile diagonal entering prefixes
__device__ float g_z1[BATCH*NIN];           // layer-1 input, compact 64x1024
__device__ float g_z2[BATCH*LSZ];           // layer-2 input, 64x4096
__device__ float g_h2[BATCH*FCN];           // layer-2 output, compact 64x512
__device__ float g_Ypart[32*BATCH*FCN > 4*BATCH*LSZ ? 32*BATCH*FCN : 4*BATCH*LSZ];

// ---------------- cumprod scan: d[0]=1, d[j]=prod_{k<j} subd[k]; also reciprocals ------------
__global__ void scan_kernel(const float* __restrict__ sA1, const float* __restrict__ sB1,
                            const float* __restrict__ sA2, const float* __restrict__ sB2) {
    const float* src; float* dst; float* inv;
    if      (blockIdx.x == 0) { src = sA1; dst = g_da1; inv = g_ida1; }
    else if (blockIdx.x == 1) { src = sB1; dst = g_db1; inv = g_idb1; }
    else if (blockIdx.x == 2) { src = sA2; dst = g_da2; inv = g_ida2; }
    else                      { src = sB2; dst = g_db2; inv = g_idb2; }

    __shared__ float part[1024];
    int tid = threadIdx.x;
    float v[4]; float p = 1.f;
#pragma unroll
    for (int j = 0; j < 4; j++) {
        int idx = tid * 4 + j;
        float s = (idx < LSZ - 1) ? src[idx] : 1.f;
        p *= s; v[j] = p;
    }
    part[tid] = p; __syncthreads();
    for (int off = 1; off < 1024; off <<= 1) {
        float x = part[tid];
        float m = (tid >= off) ? part[tid - off] : 1.f;
        __syncthreads();
        part[tid] = x * m;
        __syncthreads();
    }
    float excl = (tid == 0) ? 1.f : part[tid - 1];
    if (tid == 0) { dst[0] = 1.f; inv[0] = 1.f; }
#pragma unroll
    for (int j = 0; j < 4; j++) {
        int idx = tid * 4 + j;
        if (idx < LSZ - 1) {
            float val = excl * v[j];
            dst[idx + 1] = val;
            inv[idx + 1] = 1.0f / val;
        }
    }
}

// ---------------- prep: Gt=G*ida, Ht=H*idb, z1 = db1 * x (compact 1024) ----------------
__global__ void prep_kernel(const float* __restrict__ G1, const float* __restrict__ H1,
                            const float* __restrict__ G2, const float* __restrict__ H2,
                            const float* __restrict__ x) {
    int tid = blockIdx.x * blockDim.x + threadIdx.x;
    int j = tid & (LSZ - 1);
    if (tid < R1 * LSZ) {
        g_Gt1[tid] = G1[tid] * g_ida1[j];
        g_Ht1[tid] = H1[tid] * g_idb1[j];
    }
    if (tid < R2 * LSZ) {
        g_Gt2[tid] = G2[tid] * g_ida2[j];
        g_Ht2[tid] = H2[tid] * g_idb2[j];
    }
    if (tid < BATCH * NIN) {
        int jj = tid & (NIN - 1);
        g_z1[tid] = x[tid] * g_db1[jj];
    }
}

// ---------------- Q = Gt^T Ht + per-subtile diagonal totals ----------------
// Q[t][w]; 128x128 tile; k = blockIdx.y (t-tile), c = blockIdx.x (w-chunk), NC = ld/128.
// After mainloop, accumulators are parked in smem and 255 threads sum each local diagonal.
template <int R>
__global__ __launch_bounds__(256, 2) void qgemm_kernel(const float* __restrict__ Gt,
                                                       const float* __restrict__ Ht,
                                                       float* __restrict__ Q, int ld,
                                                       float* __restrict__ sub) {
    extern __shared__ float sh[];
    float* sG = sh;             // R x 132
    float* sH = sh + R * 132;   // R x 132   (tile reuses sh after mainloop)
    int k = blockIdx.y, c = blockIdx.x;
    int NC = ld >> 7;
    int t0 = k << 7, w0 = c << 7;
    for (int idx = threadIdx.x; idx < R * 128; idx += 256) {
        int i = idx >> 7, e = idx & 127;
        sG[i * 132 + e] = Gt[i * LSZ + t0 + e];
        sH[i * 132 + e] = Ht[i * LSZ + w0 + e];
    }
    __syncthreads();

    int tx = threadIdx.x & 15, ty = threadIdx.x >> 4;
    float acc[8][8];
#pragma unroll
    for (int u = 0; u < 8; u++)
#pragma unroll
        for (int v = 0; v < 8; v++) acc[u][v] = 0.f;

    for (int i = 0; i < R; i++) {
        float a[8], b[8];
        ((float4*)a)[0] = *(const float4*)&sG[i * 132 + ty * 4];
        ((float4*)a)[1] = *(const float4*)&sG[i * 132 + 64 + ty * 4];
        ((float4*)b)[0] = *(const float4*)&sH[i * 132 + tx * 4];
        ((float4*)b)[1] = *(const float4*)&sH[i * 132 + 64 + tx * 4];
#pragma unroll
        for (int u = 0; u < 8; u++)
#pragma unroll
            for (int v = 0; v < 8; v++) acc[u][v] = fmaf(a[u], b[v], acc[u][v]);
    }
    // global stores
#pragma unroll
    for (int u = 0; u < 8; u++) {
        int t = t0 + (u < 4 ? ty * 4 + u : 64 + ty * 4 + u - 4);
        *(float4*)&Q[(size_t)t * ld + w0 + tx * 4]      = make_float4(acc[u][0], acc[u][1], acc[u][2], acc[u][3]);
        *(float4*)&Q[(size_t)t * ld + w0 + 64 + tx * 4] = make_float4(acc[u][4], acc[u][5], acc[u][6], acc[u][7]);
    }
    __syncthreads();   // everyone done reading sG/sH
    // park tile in smem (reuse sh): 128 x 132
    float* sT = sh;
#pragma unroll
    for (int u = 0; u < 8; u++) {
        int row = (u < 4 ? ty * 4 + u : 64 + ty * 4 + u - 4);
        *(float4*)&sT[row * 132 + tx * 4]      = make_float4(acc[u][0], acc[u][1], acc[u][2], acc[u][3]);
        *(float4*)&sT[row * 132 + 64 + tx * 4] = make_float4(acc[u][4], acc[u][5], acc[u][6], acc[u][7]);
    }
    __syncthreads();
    // per-diagonal totals: local diag dl = tid-127 in [-127,127]
    int tid = threadIdx.x;
    if (tid < 255) {
        int dl = tid - 127;
        float s = 0.f;
#pragma unroll 4
        for (int row = 0; row < 128; row++) {
            int col = row - dl;
            if ((unsigned)col < 128u) s += sT[row * 132 + col];
        }
        sub[(k * NC + c) * 256 + tid] = s;
    } else {
        sub[(k * NC + c) * 256 + 255] = 0.f;
    }
}

// ---------------- prefix over subtile totals along each diagonal ----------------
// pref[(k*NC+c)*256 + j] = sum of sub over all subtiles strictly earlier on global diagonal
// d = 128*(k-c) + (j-127). Earlier = k2<k (any chunk) or k2==k, c2<c. At most 2 chunk
// candidates per t-tile: q = k2-c2 in {d>>7, (d+127)>>7} (arithmetic shift = floor div).
__global__ void prefix_kernel(const float* __restrict__ sub, float* __restrict__ pref,
                              int NC) {
    int j = threadIdx.x;
    int sidx = blockIdx.x;            // k*NC + c
    int k = sidx / NC, c = sidx - k * NC;
    if (j == 255) { pref[sidx * 256 + 255] = 0.f; return; }
    int d = ((k - c) << 7) + (j - 127);
    int qlo = d >> 7;
    int qhi = (d + 127) >> 7;
    float acc = 0.f;
    for (int k2 = 0; k2 < k; k2++) {
        int c2 = k2 - qlo;
        if (c2 >= 0 && c2 < NC) acc += sub[(k2 * NC + c2) * 256 + (d - (qlo << 7)) + 127];
        if (qhi != qlo) {
            c2 = k2 - qhi;
            if (c2 >= 0 && c2 < NC) acc += sub[(k2 * NC + c2) * 256 + (d - (qhi << 7)) + 127];
        }
    }
    {   // same t-tile, earlier chunks
        int c2 = k - qlo;
        if (c2 >= 0 && c2 < c) acc += sub[(k * NC + c2) * 256 + (d - (qlo << 7)) + 127];
        if (qhi != qlo) {
            c2 = k - qhi;
            if (c2 >= 0 && c2 < c) acc += sub[(k * NC + c2) * 256 + (d - (qhi << 7)) + 127];
        }
    }
    pref[sidx * 256 + j] = acc;
}

// ---------------- main GEMM with fused in-smem diagonal cumsum ----------------
// Ypart[slice][b][t] = sum_{w in slice} M[t][w] z[b][w], where M = diag-cumsum(Q).
// Loads raw Q tile, seeds each local diagonal from g_pref, cumsums in smem, then FMA loop.
__global__ __launch_bounds__(256, 2) void skewgemm_kernel(const float* __restrict__ Q, int ld,
                                                          const float* __restrict__ z, int zld,
                                                          const float* __restrict__ pref,
                                                          float* __restrict__ Ypart, int Tdim,
                                                          int nchunk) {
    extern __shared__ float sh[];
    float* sM = sh;                 // 128 x 132
    float* sz = sh + 128 * 132;     // 64 x 132
    int k = blockIdx.x;
    int t0 = k << 7;
    int NC = ld >> 7;
    int c0 = blockIdx.y * nchunk;
    int tx = threadIdx.x & 15, ty = threadIdx.x >> 4;
    int tid = threadIdx.x;
    float acc[8][4];
#pragma unroll
    for (int u = 0; u < 8; u++)
#pragma unroll
        for (int v = 0; v < 4; v++) acc[u][v] = 0.f;

    for (int cc = 0; cc < nchunk; cc++) {
        int c = c0 + cc;
        int w0 = c << 7;
        for (int idx = tid; idx < 128 * 32; idx += 256) {
            int row = idx >> 5, c4 = idx & 31;
            float4 m4 = *(const float4*)&Q[(size_t)(t0 + row) * ld + w0 + 4 * c4];
            *(float4*)&sM[row * 132 + 4 * c4] = m4;
        }
        for (int idx = tid; idx < 64 * 32; idx += 256) {
            int b = idx >> 5, c4 = idx & 31;
            float4 z4 = *(const float4*)&z[(size_t)b * zld + w0 + 4 * c4];
            *(float4*)&sz[b * 132 + 4 * c4] = z4;
        }
        __syncthreads();
        // in-smem segmented diagonal cumsum on sM
        if (tid < 255) {
            int dl = tid - 127;
            float a = pref[(k * NC + c) * 256 + tid];
#pragma unroll 4
            for (int row = 0; row < 128; row++) {
                int col = row - dl;
                if ((unsigned)col < 128u) {
                    a += sM[row * 132 + col];
                    sM[row * 132 + col] = a;
                }
            }
        }
        __syncthreads();
#pragma unroll 4
        for (int ww = 0; ww < 128; ww++) {
            float a[8], zb[4];
#pragma unroll
            for (int u = 0; u < 8; u++) a[u] = sM[(tx + 16 * u) * 132 + ww];
#pragma unroll
            for (int v = 0; v < 4; v++) zb[v] = sz[(ty + 16 * v) * 132 + ww];
#pragma unroll
            for (int u = 0; u < 8; u++)
#pragma unroll
                for (int v = 0; v < 4; v++) acc[u][v] = fmaf(a[u], zb[v], acc[u][v]);
        }
        __syncthreads();
    }
#pragma unroll
    for (int u = 0; u < 8; u++) {
        int t = t0 + tx + 16 * u;
#pragma unroll
        for (int v = 0; v < 4; v++) {
            int b = ty + 16 * v;
            Ypart[((size_t)blockIdx.y * BATCH + b) * Tdim + t] = acc[u][v];
        }
    }
}

// ---------------- epilogue 1: reduce 4 partials, z2 = relu(da1*s + b1) * db2 (full 4096) -------
__global__ void epilogue1_kernel(const float* __restrict__ bias) {
    int i4 = blockIdx.x * 256 + threadIdx.x;
    if (i4 >= BATCH * LSZ / 4) return;
    const float4* Yp = (const float4*)g_Ypart;
    float4 s = Yp[i4];
#pragma unroll
    for (int k = 1; k < 4; k++) {
        float4 p = Yp[(size_t)k * (BATCH * LSZ / 4) + i4];
        s.x += p.x; s.y += p.y; s.z += p.z; s.w += p.w;
    }
    int t = (i4 * 4) & (LSZ - 1);
    float4 dav = *(const float4*)&g_da1[t];
    float4 bv  = *(const float4*)&bias[t];
    float4 db  = *(const float4*)&g_db2[t];
    float4 h;
    h.x = fmaxf(dav.x * s.x + bv.x, 0.f) * db.x;
    h.y = fmaxf(dav.y * s.y + bv.y, 0.f) * db.y;
    h.z = fmaxf(dav.z * s.z + bv.z, 0.f) * db.z;
    h.w = fmaxf(dav.w * s.w + bv.w, 0.f) * db.w;
    ((float4*)g_z2)[i4] = h;
}

// ---------------- epilogue 2: reduce 32 partials over 64x512, h2 = relu(da2*s + b2) -----------
__global__ void epilogue2_kernel(const float* __restrict__ bias) {
    int i4 = blockIdx.x * 256 + threadIdx.x;
    if (i4 >= BATCH * FCN / 4) return;
    const float4* Yp = (const float4*)g_Ypart;
    float4 s = Yp[i4];
#pragma unroll
    for (int k = 1; k < 32; k++) {
        float4 p = Yp[(size_t)k * (BATCH * FCN / 4) + i4];
        s.x += p.x; s.y += p.y; s.z += p.z; s.w += p.w;
    }
    int t = (i4 * 4) & (FCN - 1);
    float4 dav = *(const float4*)&g_da2[t];
    float4 bv  = *(const float4*)&bias[t];
    float4 h;
    h.x = fmaxf(dav.x * s.x + bv.x, 0.f);
    h.y = fmaxf(dav.y * s.y + bv.y, 0.f);
    h.z = fmaxf(dav.z * s.z + bv.z, 0.f);
    h.w = fmaxf(dav.w * s.w + bv.w, 0.f);
    ((float4*)g_h2)[i4] = h;
}

// ---------------- logits: out[b][c] = h2[b] . W[c] + bl[c] ----------------
__global__ void logits_kernel(const float* __restrict__ W, const float* __restrict__ bl,
                              float* __restrict__ out) {
    int b = blockIdx.x;
    int cls = threadIdx.x >> 5;
    int lane = threadIdx.x & 31;
    float s = 0.f;
#pragma unroll
    for (int m = 0; m < 16; m++) {
        int j = lane + 32 * m;
        s = fmaf(g_h2[b * FCN + j], W[cls * FCN + j], s);
    }
#pragma unroll
    for (int off = 16; off; off >>= 1) s += __shfl_down_sync(0xffffffffu, s, off);
    if (lane == 0) out[b * NCLS + cls] = s + bl[cls];
}

// ---------------- launch ----------------
extern "C" void kernel_launch(void* const* d_in, const int* in_sizes, int n_in,
                              void* d_out, int out_size) {
    const float* x    = (const float*)d_in[0];
    const float* G1   = (const float*)d_in[1];
    const float* H1   = (const float*)d_in[2];
    const float* sdA1 = (const float*)d_in[3];
    const float* sdB1 = (const float*)d_in[4];
    const float* b1   = (const float*)d_in[5];
    const float* G2   = (const float*)d_in[6];
    const float* H2   = (const float*)d_in[7];
    const float* sdA2 = (const float*)d_in[8];
    const float* sdB2 = (const float*)d_in[9];
    const float* b2   = (const float*)d_in[10];
    const float* W    = (const float*)d_in[11];
    const float* bl   = (const float*)d_in[12];
    float* out = (float*)d_out;

    const int QSM = 128 * 132 * 4;               // 67584 (tile park; >= 2*R*132*4 for R<=48)
    const int GSM = (128 * 132 + 64 * 132) * 4;  // 101376

    cudaFuncSetAttribute(qgemm_kernel<R1>, cudaFuncAttributeMaxDynamicSharedMemorySize, QSM);
    cudaFuncSetAttribute(qgemm_kernel<R2>, cudaFuncAttributeMaxDynamicSharedMemorySize, QSM);
    cudaFuncSetAttribute(skewgemm_kernel, cudaFuncAttributeMaxDynamicSharedMemorySize, GSM);

    float* Mbuf;  cudaGetSymbolAddress((void**)&Mbuf, g_M);
    float* Sub;   cudaGetSymbolAddress((void**)&Sub, g_sub);
    float* Pref;  cudaGetSymbolAddress((void**)&Pref, g_pref);
    float* Ypart; cudaGetSymbolAddress((void**)&Ypart, g_Ypart);
    float* z1;    cudaGetSymbolAddress((void**)&z1, g_z1);
    float* z2;    cudaGetSymbolAddress((void**)&z2, g_z2);
    float* Gt1;   cudaGetSymbolAddress((void**)&Gt1, g_Gt1);
    float* Ht1;   cudaGetSymbolAddress((void**)&Ht1, g_Ht1);
    float* Gt2;   cudaGetSymbolAddress((void**)&Gt2, g_Gt2);
    float* Ht2;   cudaGetSymbolAddress((void**)&Ht2, g_Ht2);

    scan_kernel<<<4, 1024>>>(sdA1, sdB1, sdA2, sdB2);
    prep_kernel<<<1024, 256>>>(G1, H1, G2, H2, x);

    // ---- layer 1: strip 4096 x 1024 (input zero-padded beyond 1024); NC=8 ----
    qgemm_kernel<R1><<<dim3(8, 32), 256, QSM>>>(Gt1, Ht1, Mbuf, 1024, Sub);
    prefix_kernel<<<256, 256>>>(Sub, Pref, 8);
    skewgemm_kernel<<<dim3(32, 4), 256, GSM>>>(Mbuf, 1024, z1, 1024, Pref, Ypart, LSZ, 2);
    epilogue1_kernel<<<256, 256>>>(b1);

    // ---- layer 2: strip 512 x 4096 (only first 512 outputs used); NC=32 ----
    qgemm_kernel<R2><<<dim3(32, 4), 256, QSM>>>(Gt2, Ht2, Mbuf, 4096, Sub);
    prefix_kernel<<<128, 256>>>(Sub, Pref, 32);
    skewgemm_kernel<<<dim3(4, 32), 256, GSM>>>(Mbuf, 4096, z2, 4096, Pref, Ypart, FCN, 1);
    epilogue2_kernel<<<32, 256>>>(b2);

    logits_kernel<<<64, 320>>>(W, bl, out);
}

// round 9
// speedup vs baseline: 4.6742x; 1.0178x over previous
#include <cuda_runtime.h>

#define LSZ   4096
#define BATCH 64
#define R1    48
#define R2    16
#define NIN   1024
#define FCN   512
#define NCLS  10

// ---------------- scratch (device globals; no allocation allowed) ----------------
__device__ float g_da1[LSZ], g_db1[LSZ], g_da2[LSZ], g_db2[LSZ];
__device__ float g_ida1[LSZ], g_idb1[LSZ], g_ida2[LSZ], g_idb2[LSZ];
__device__ float g_Gt1[R1*LSZ], g_Ht1[R1*LSZ];
__device__ float g_Gt2[R2*LSZ], g_Ht2[R2*LSZ];
__device__ float g_M[(size_t)LSZ*1024];     // 16MB Q strip; layer2 uses 512*4096 = 8MB
__device__ float g_sub[256*256];            // per-subtile diagonal totals (max 32*8 subtiles)
__device__ float g_z1[BATCH*NIN];           // layer-1 input, compact 64x1024
__device__ float g_z2[BATCH*LSZ];           // layer-2 input, 64x4096
__device__ float g_Ypart[32*BATCH*FCN > 4*BATCH*LSZ ? 32*BATCH*FCN : 4*BATCH*LSZ];

// ---------------- cumprod scan: d[0]=1, d[j]=prod_{k<j} subd[k]; also reciprocals ------------
__global__ void scan_kernel(const float* __restrict__ sA1, const float* __restrict__ sB1,
                            const float* __restrict__ sA2, const float* __restrict__ sB2) {
    const float* src; float* dst; float* inv;
    if      (blockIdx.x == 0) { src = sA1; dst = g_da1; inv = g_ida1; }
    else if (blockIdx.x == 1) { src = sB1; dst = g_db1; inv = g_idb1; }
    else if (blockIdx.x == 2) { src = sA2; dst = g_da2; inv = g_ida2; }
    else                      { src = sB2; dst = g_db2; inv = g_idb2; }

    __shared__ float part[1024];
    int tid = threadIdx.x;
    float v[4]; float p = 1.f;
#pragma unroll
    for (int j = 0; j < 4; j++) {
        int idx = tid * 4 + j;
        float s = (idx < LSZ - 1) ? src[idx] : 1.f;
        p *= s; v[j] = p;
    }
    part[tid] = p; __syncthreads();
    for (int off = 1; off < 1024; off <<= 1) {
        float x = part[tid];
        float m = (tid >= off) ? part[tid - off] : 1.f;
        __syncthreads();
        part[tid] = x * m;
        __syncthreads();
    }
    float excl = (tid == 0) ? 1.f : part[tid - 1];
    if (tid == 0) { dst[0] = 1.f; inv[0] = 1.f; }
#pragma unroll
    for (int j = 0; j < 4; j++) {
        int idx = tid * 4 + j;
        if (idx < LSZ - 1) {
            float val = excl * v[j];
            dst[idx + 1] = val;
            inv[idx + 1] = 1.0f / val;
        }
    }
}

// ---------------- prep: Gt=G*ida, Ht=H*idb, z1 = db1 * x (compact 1024) ----------------
__global__ void prep_kernel(const float* __restrict__ G1, const float* __restrict__ H1,
                            const float* __restrict__ G2, const float* __restrict__ H2,
                            const float* __restrict__ x) {
    int tid = blockIdx.x * blockDim.x + threadIdx.x;
    int j = tid & (LSZ - 1);
    if (tid < R1 * LSZ) {
        g_Gt1[tid] = G1[tid] * g_ida1[j];
        g_Ht1[tid] = H1[tid] * g_idb1[j];
    }
    if (tid < R2 * LSZ) {
        g_Gt2[tid] = G2[tid] * g_ida2[j];
        g_Ht2[tid] = H2[tid] * g_idb2[j];
    }
    if (tid < BATCH * NIN) {
        int jj = tid & (NIN - 1);
        g_z1[tid] = x[tid] * g_db1[jj];
    }
}

// ---------------- Q = Gt^T Ht + per-subtile diagonal totals ----------------
// Q[t][w]; 128x128 tile; k = blockIdx.y (t-tile), c = blockIdx.x (w-chunk), NC = ld/128.
// After mainloop, accumulators are parked in smem and 255 threads sum each local diagonal.
template <int R>
__global__ __launch_bounds__(256, 2) void qgemm_kernel(const float* __restrict__ Gt,
                                                       const float* __restrict__ Ht,
                                                       float* __restrict__ Q, int ld,
                                                       float* __restrict__ sub) {
    extern __shared__ float sh[];
    float* sG = sh;             // R x 132
    float* sH = sh + R * 132;   // R x 132   (tile reuses sh after mainloop)
    int k = blockIdx.y, c = blockIdx.x;
    int NC = ld >> 7;
    int t0 = k << 7, w0 = c << 7;
    for (int idx = threadIdx.x; idx < R * 128; idx += 256) {
        int i = idx >> 7, e = idx & 127;
        sG[i * 132 + e] = Gt[i * LSZ + t0 + e];
        sH[i * 132 + e] = Ht[i * LSZ + w0 + e];
    }
    __syncthreads();

    int tx = threadIdx.x & 15, ty = threadIdx.x >> 4;
    float acc[8][8];
#pragma unroll
    for (int u = 0; u < 8; u++)
#pragma unroll
        for (int v = 0; v < 8; v++) acc[u][v] = 0.f;

    for (int i = 0; i < R; i++) {
        float a[8], b[8];
        ((float4*)a)[0] = *(const float4*)&sG[i * 132 + ty * 4];
        ((float4*)a)[1] = *(const float4*)&sG[i * 132 + 64 + ty * 4];
        ((float4*)b)[0] = *(const float4*)&sH[i * 132 + tx * 4];
        ((float4*)b)[1] = *(const float4*)&sH[i * 132 + 64 + tx * 4];
#pragma unroll
        for (int u = 0; u < 8; u++)
#pragma unroll
            for (int v = 0; v < 8; v++) acc[u][v] = fmaf(a[u], b[v], acc[u][v]);
    }
    // global stores
#pragma unroll
    for (int u = 0; u < 8; u++) {
        int t = t0 + (u < 4 ? ty * 4 + u : 64 + ty * 4 + u - 4);
        *(float4*)&Q[(size_t)t * ld + w0 + tx * 4]      = make_float4(acc[u][0], acc[u][1], acc[u][2], acc[u][3]);
        *(float4*)&Q[(size_t)t * ld + w0 + 64 + tx * 4] = make_float4(acc[u][4], acc[u][5], acc[u][6], acc[u][7]);
    }
    __syncthreads();   // everyone done reading sG/sH
    // park tile in smem (reuse sh): 128 x 132
    float* sT = sh;
#pragma unroll
    for (int u = 0; u < 8; u++) {
        int row = (u < 4 ? ty * 4 + u : 64 + ty * 4 + u - 4);
        *(float4*)&sT[row * 132 + tx * 4]      = make_float4(acc[u][0], acc[u][1], acc[u][2], acc[u][3]);
        *(float4*)&sT[row * 132 + 64 + tx * 4] = make_float4(acc[u][4], acc[u][5], acc[u][6], acc[u][7]);
    }
    __syncthreads();
    // per-diagonal totals: local diag dl = tid-127 in [-127,127]
    int tid = threadIdx.x;
    if (tid < 255) {
        int dl = tid - 127;
        float s = 0.f;
#pragma unroll 4
        for (int row = 0; row < 128; row++) {
            int col = row - dl;
            if ((unsigned)col < 128u) s += sT[row * 132 + col];
        }
        sub[(k * NC + c) * 256 + tid] = s;
    } else {
        sub[(k * NC + c) * 256 + 255] = 0.f;
    }
}

// ---------------- main GEMM with fused prefix + in-smem diagonal cumsum ----------------
// Ypart[slice][b][t] = sum_{w in slice} M[t][w] z[b][w], where M = diag-cumsum(Q).
// Loads raw Q tile; while loads are in flight, computes the diagonal entering prefix from
// g_sub (all subtiles strictly earlier on the global diagonal); cumsums in smem; FMA loop.
__global__ __launch_bounds__(256, 2) void skewgemm_kernel(const float* __restrict__ Q, int ld,
                                                          const float* __restrict__ z, int zld,
                                                          const float* __restrict__ sub,
                                                          float* __restrict__ Ypart, int Tdim,
                                                          int nchunk) {
    extern __shared__ float sh[];
    float* sM = sh;                 // 128 x 132
    float* sz = sh + 128 * 132;     // 64 x 132
    int k = blockIdx.x;
    int t0 = k << 7;
    int NC = ld >> 7;
    int c0 = blockIdx.y * nchunk;
    int tx = threadIdx.x & 15, ty = threadIdx.x >> 4;
    int tid = threadIdx.x;
    float acc[8][4];
#pragma unroll
    for (int u = 0; u < 8; u++)
#pragma unroll
        for (int v = 0; v < 4; v++) acc[u][v] = 0.f;

    for (int cc = 0; cc < nchunk; cc++) {
        int c = c0 + cc;
        int w0 = c << 7;
        for (int idx = tid; idx < 128 * 32; idx += 256) {
            int row = idx >> 5, c4 = idx & 31;
            float4 m4 = *(const float4*)&Q[(size_t)(t0 + row) * ld + w0 + 4 * c4];
            *(float4*)&sM[row * 132 + 4 * c4] = m4;
        }
        for (int idx = tid; idx < 64 * 32; idx += 256) {
            int b = idx >> 5, c4 = idx & 31;
            float4 z4 = *(const float4*)&z[(size_t)b * zld + w0 + 4 * c4];
            *(float4*)&sz[b * 132 + 4 * c4] = z4;
        }
        // ---- prefix for (k,c), overlapped with the tile loads above ----
        // global diag d = 128*(k-c) + (tid-127); earlier subtiles: k2<k any chunk, or k2==k c2<c.
        // chunk candidates per t-tile: q = k2-c2 in {d>>7, (d+127)>>7}.
        float pacc = 0.f;
        if (tid < 255) {
            int d = ((k - c) << 7) + (tid - 127);
            int qlo = d >> 7;
            int qhi = (d + 127) >> 7;
            int jlo = (d - (qlo << 7)) + 127;
            int jhi = (d - (qhi << 7)) + 127;
            for (int k2 = 0; k2 < k; k2++) {
                int c2 = k2 - qlo;
                if (c2 >= 0 && c2 < NC) pacc += sub[(k2 * NC + c2) * 256 + jlo];
                if (qhi != qlo) {
                    c2 = k2 - qhi;
                    if (c2 >= 0 && c2 < NC) pacc += sub[(k2 * NC + c2) * 256 + jhi];
                }
            }
            int c2 = k - qlo;
            if (c2 >= 0 && c2 < c) pacc += sub[(k * NC + c2) * 256 + jlo];
            if (qhi != qlo) {
                c2 = k - qhi;
                if (c2 >= 0 && c2 < c) pacc += sub[(k * NC + c2) * 256 + jhi];
            }
        }
        __syncthreads();
        // in-smem segmented diagonal cumsum on sM, seeded by pacc
        if (tid < 255) {
            int dl = tid - 127;
            float a = pacc;
#pragma unroll 4
            for (int row = 0; row < 128; row++) {
                int col = row - dl;
                if ((unsigned)col < 128u) {
                    a += sM[row * 132 + col];
                    sM[row * 132 + col] = a;
                }
            }
        }
        __syncthreads();
#pragma unroll 4
        for (int ww = 0; ww < 128; ww++) {
            float a[8], zb[4];
#pragma unroll
            for (int u = 0; u < 8; u++) a[u] = sM[(tx + 16 * u) * 132 + ww];
#pragma unroll
            for (int v = 0; v < 4; v++) zb[v] = sz[(ty + 16 * v) * 132 + ww];
#pragma unroll
            for (int u = 0; u < 8; u++)
#pragma unroll
                for (int v = 0; v < 4; v++) acc[u][v] = fmaf(a[u], zb[v], acc[u][v]);
        }
        __syncthreads();
    }
#pragma unroll
    for (int u = 0; u < 8; u++) {
        int t = t0 + tx + 16 * u;
#pragma unroll
        for (int v = 0; v < 4; v++) {
            int b = ty + 16 * v;
            Ypart[((size_t)blockIdx.y * BATCH + b) * Tdim + t] = acc[u][v];
        }
    }
}

// ---------------- epilogue 1: reduce 4 partials, z2 = relu(da1*s + b1) * db2 (full 4096) -------
__global__ void epilogue1_kernel(const float* __restrict__ bias) {
    int i4 = blockIdx.x * 256 + threadIdx.x;
    if (i4 >= BATCH * LSZ / 4) return;
    const float4* Yp = (const float4*)g_Ypart;
    float4 s = Yp[i4];
#pragma unroll
    for (int k = 1; k < 4; k++) {
        float4 p = Yp[(size_t)k * (BATCH * LSZ / 4) + i4];
        s.x += p.x; s.y += p.y; s.z += p.z; s.w += p.w;
    }
    int t = (i4 * 4) & (LSZ - 1);
    float4 dav = *(const float4*)&g_da1[t];
    float4 bv  = *(const float4*)&bias[t];
    float4 db  = *(const float4*)&g_db2[t];
    float4 h;
    h.x = fmaxf(dav.x * s.x + bv.x, 0.f) * db.x;
    h.y = fmaxf(dav.y * s.y + bv.y, 0.f) * db.y;
    h.z = fmaxf(dav.z * s.z + bv.z, 0.f) * db.z;
    h.w = fmaxf(dav.w * s.w + bv.w, 0.f) * db.w;
    ((float4*)g_z2)[i4] = h;
}

// ---------------- fused epilogue2 + logits ----------------
// block b: h2[t] = relu(da2*sum_k Ypart[k][b][t] + b2[t]) into smem, then 10 warps
// each compute one class dot product over 512.
__global__ __launch_bounds__(512) void epilogits_kernel(const float* __restrict__ bias,
                                                        const float* __restrict__ W,
                                                        const float* __restrict__ bl,
                                                        float* __restrict__ out) {
    __shared__ float sh2[FCN];
    int b = blockIdx.x;
    int t = threadIdx.x;            // 512 threads = one t each
    float s = 0.f;
#pragma unroll
    for (int k = 0; k < 32; k++) s += g_Ypart[(size_t)k * BATCH * FCN + b * FCN + t];
    sh2[t] = fmaxf(g_da2[t] * s + bias[t], 0.f);
    __syncthreads();
    int cls = t >> 5;
    int lane = t & 31;
    if (cls < NCLS) {
        float acc = 0.f;
#pragma unroll
        for (int m = 0; m < 16; m++) {
            int j = lane + 32 * m;
            acc = fmaf(sh2[j], W[cls * FCN + j], acc);
        }
#pragma unroll
        for (int off = 16; off; off >>= 1) acc += __shfl_down_sync(0xffffffffu, acc, off);
        if (lane == 0) out[b * NCLS + cls] = acc + bl[cls];
    }
}

// ---------------- launch ----------------
extern "C" void kernel_launch(void* const* d_in, const int* in_sizes, int n_in,
                              void* d_out, int out_size) {
    const float* x    = (const float*)d_in[0];
    const float* G1   = (const float*)d_in[1];
    const float* H1   = (const float*)d_in[2];
    const float* sdA1 = (const float*)d_in[3];
    const float* sdB1 = (const float*)d_in[4];
    const float* b1   = (const float*)d_in[5];
    const float* G2   = (const float*)d_in[6];
    const float* H2   = (const float*)d_in[7];
    const float* sdA2 = (const float*)d_in[8];
    const float* sdB2 = (const float*)d_in[9];
    const float* b2   = (const float*)d_in[10];
    const float* W    = (const float*)d_in[11];
    const float* bl   = (const float*)d_in[12];
    float* out = (float*)d_out;

    const int QSM = 128 * 132 * 4;               // 67584 (tile park; >= 2*R*132*4 for R<=48)
    const int GSM = (128 * 132 + 64 * 132) * 4;  // 101376

    cudaFuncSetAttribute(qgemm_kernel<R1>, cudaFuncAttributeMaxDynamicSharedMemorySize, QSM);
    cudaFuncSetAttribute(qgemm_kernel<R2>, cudaFuncAttributeMaxDynamicSharedMemorySize, QSM);
    cudaFuncSetAttribute(skewgemm_kernel, cudaFuncAttributeMaxDynamicSharedMemorySize, GSM);

    float* Mbuf;  cudaGetSymbolAddress((void**)&Mbuf, g_M);
    float* Sub;   cudaGetSymbolAddress((void**)&Sub, g_sub);
    float* Ypart; cudaGetSymbolAddress((void**)&Ypart, g_Ypart);
    float* z1;    cudaGetSymbolAddress((void**)&z1, g_z1);
    float* z2;    cudaGetSymbolAddress((void**)&z2, g_z2);
    float* Gt1;   cudaGetSymbolAddress((void**)&Gt1, g_Gt1);
    float* Ht1;   cudaGetSymbolAddress((void**)&Ht1, g_Ht1);
    float* Gt2;   cudaGetSymbolAddress((void**)&Gt2, g_Gt2);
    float* Ht2;   cudaGetSymbolAddress((void**)&Ht2, g_Ht2);

    scan_kernel<<<4, 1024>>>(sdA1, sdB1, sdA2, sdB2);
    prep_kernel<<<1024, 256>>>(G1, H1, G2, H2, x);

    // ---- layer 1: strip 4096 x 1024 (input zero-padded beyond 1024); NC=8 ----
    qgemm_kernel<R1><<<dim3(8, 32), 256, QSM>>>(Gt1, Ht1, Mbuf, 1024, Sub);
    skewgemm_kernel<<<dim3(32, 4), 256, GSM>>>(Mbuf, 1024, z1, 1024, Sub, Ypart, LSZ, 2);
    epilogue1_kernel<<<256, 256>>>(b1);

    // ---- layer 2: strip 512 x 4096 (only first 512 outputs used); NC=32 ----
    qgemm_kernel<R2><<<dim3(32, 4), 256, QSM>>>(Gt2, Ht2, Mbuf, 4096, Sub);
    skewgemm_kernel<<<dim3(4, 32), 256, GSM>>>(Mbuf, 4096, z2, 4096, Sub, Ypart, FCN, 1);
    epilogits_kernel<<<64, 512>>>(b2, W, bl, out);

    logits_kernel_unused:;
}

// round 10
// speedup vs baseline: 4.7748x; 1.0215x over previous
#include <cuda_runtime.h>

#define LSZ   4096
#define BATCH 64
#define R1    48
#define R2    16
#define NIN   1024
#define FCN   512
#define NCLS  10

// ---------------- scratch (device globals; no allocation allowed) ----------------
__device__ float g_da1[LSZ], g_db1[LSZ], g_da2[LSZ], g_db2[LSZ];
__device__ float g_ida1[LSZ], g_idb1[LSZ], g_ida2[LSZ], g_idb2[LSZ];
__device__ float g_Gt1[R1*LSZ], g_Ht1[R1*LSZ];
__device__ float g_Gt2[R2*LSZ], g_Ht2[R2*LSZ];
__device__ float g_M[(size_t)LSZ*1024];     // 16MB Q strip; layer2 uses 512*4096 = 8MB
__device__ float g_sub[256*256];            // per-subtile diagonal totals (max 32*8 subtiles)
__device__ float g_z1[BATCH*NIN];           // layer-1 input, compact 64x1024
__device__ float g_z2[BATCH*LSZ];           // layer-2 input, 64x4096
__device__ float g_Ypart[8*BATCH*LSZ];      // split-K partials: L1 8 slices, L2 32 slices of 64x512

// ---------------- cumprod scan: d[0]=1, d[j]=prod_{k<j} subd[k]; also reciprocals ------------
__global__ void scan_kernel(const float* __restrict__ sA1, const float* __restrict__ sB1,
                            const float* __restrict__ sA2, const float* __restrict__ sB2) {
    const float* src; float* dst; float* inv;
    if      (blockIdx.x == 0) { src = sA1; dst = g_da1; inv = g_ida1; }
    else if (blockIdx.x == 1) { src = sB1; dst = g_db1; inv = g_idb1; }
    else if (blockIdx.x == 2) { src = sA2; dst = g_da2; inv = g_ida2; }
    else                      { src = sB2; dst = g_db2; inv = g_idb2; }

    __shared__ float part[1024];
    int tid = threadIdx.x;
    float v[4]; float p = 1.f;
#pragma unroll
    for (int j = 0; j < 4; j++) {
        int idx = tid * 4 + j;
        float s = (idx < LSZ - 1) ? src[idx] : 1.f;
        p *= s; v[j] = p;
    }
    part[tid] = p; __syncthreads();
    for (int off = 1; off < 1024; off <<= 1) {
        float x = part[tid];
        float m = (tid >= off) ? part[tid - off] : 1.f;
        __syncthreads();
        part[tid] = x * m;
        __syncthreads();
    }
    float excl = (tid == 0) ? 1.f : part[tid - 1];
    if (tid == 0) { dst[0] = 1.f; inv[0] = 1.f; }
#pragma unroll
    for (int j = 0; j < 4; j++) {
        int idx = tid * 4 + j;
        if (idx < LSZ - 1) {
            float val = excl * v[j];
            dst[idx + 1] = val;
            inv[idx + 1] = 1.0f / val;
        }
    }
}

// ---------------- prep: Gt=G*ida, Ht=H*idb, z1 = db1 * x (compact 1024) ----------------
__global__ void prep_kernel(const float* __restrict__ G1, const float* __restrict__ H1,
                            const float* __restrict__ G2, const float* __restrict__ H2,
                            const float* __restrict__ x) {
    int tid = blockIdx.x * blockDim.x + threadIdx.x;
    int j = tid & (LSZ - 1);
    if (tid < R1 * LSZ) {
        g_Gt1[tid] = G1[tid] * g_ida1[j];
        g_Ht1[tid] = H1[tid] * g_idb1[j];
    }
    if (tid < R2 * LSZ) {
        g_Gt2[tid] = G2[tid] * g_ida2[j];
        g_Ht2[tid] = H2[tid] * g_idb2[j];
    }
    if (tid < BATCH * NIN) {
        int jj = tid & (NIN - 1);
        g_z1[tid] = x[tid] * g_db1[jj];
    }
}

// ---------------- Q = Gt^T Ht + per-subtile diagonal totals ----------------
// Q[t][w]; 128x128 tile; k = blockIdx.y (t-tile), c = blockIdx.x (w-chunk), NC = ld/128.
// After mainloop, accumulators are parked in smem and 255 threads sum each local diagonal.
template <int R>
__global__ __launch_bounds__(256, 2) void qgemm_kernel(const float* __restrict__ Gt,
                                                       const float* __restrict__ Ht,
                                                       float* __restrict__ Q, int ld,
                                                       float* __restrict__ sub) {
    extern __shared__ float sh[];
    float* sG = sh;             // R x 132
    float* sH = sh + R * 132;   // R x 132   (tile reuses sh after mainloop)
    int k = blockIdx.y, c = blockIdx.x;
    int NC = ld >> 7;
    int t0 = k << 7, w0 = c << 7;
    for (int idx = threadIdx.x; idx < R * 128; idx += 256) {
        int i = idx >> 7, e = idx & 127;
        sG[i * 132 + e] = Gt[i * LSZ + t0 + e];
        sH[i * 132 + e] = Ht[i * LSZ + w0 + e];
    }
    __syncthreads();

    int tx = threadIdx.x & 15, ty = threadIdx.x >> 4;
    float acc[8][8];
#pragma unroll
    for (int u = 0; u < 8; u++)
#pragma unroll
        for (int v = 0; v < 8; v++) acc[u][v] = 0.f;

    for (int i = 0; i < R; i++) {
        float a[8], b[8];
        ((float4*)a)[0] = *(const float4*)&sG[i * 132 + ty * 4];
        ((float4*)a)[1] = *(const float4*)&sG[i * 132 + 64 + ty * 4];
        ((float4*)b)[0] = *(const float4*)&sH[i * 132 + tx * 4];
        ((float4*)b)[1] = *(const float4*)&sH[i * 132 + 64 + tx * 4];
#pragma unroll
        for (int u = 0; u < 8; u++)
#pragma unroll
            for (int v = 0; v < 8; v++) acc[u][v] = fmaf(a[u], b[v], acc[u][v]);
    }
    // global stores
#pragma unroll
    for (int u = 0; u < 8; u++) {
        int t = t0 + (u < 4 ? ty * 4 + u : 64 + ty * 4 + u - 4);
        *(float4*)&Q[(size_t)t * ld + w0 + tx * 4]      = make_float4(acc[u][0], acc[u][1], acc[u][2], acc[u][3]);
        *(float4*)&Q[(size_t)t * ld + w0 + 64 + tx * 4] = make_float4(acc[u][4], acc[u][5], acc[u][6], acc[u][7]);
    }
    __syncthreads();   // everyone done reading sG/sH
    // park tile in smem (reuse sh): 128 x 132
    float* sT = sh;
#pragma unroll
    for (int u = 0; u < 8; u++) {
        int row = (u < 4 ? ty * 4 + u : 64 + ty * 4 + u - 4);
        *(float4*)&sT[row * 132 + tx * 4]      = make_float4(acc[u][0], acc[u][1], acc[u][2], acc[u][3]);
        *(float4*)&sT[row * 132 + 64 + tx * 4] = make_float4(acc[u][4], acc[u][5], acc[u][6], acc[u][7]);
    }
    __syncthreads();
    // per-diagonal totals: local diag dl = tid-127 in [-127,127]
    int tid = threadIdx.x;
    if (tid < 255) {
        int dl = tid - 127;
        float s = 0.f;
#pragma unroll 4
        for (int row = 0; row < 128; row++) {
            int col = row - dl;
            if ((unsigned)col < 128u) s += sT[row * 132 + col];
        }
        sub[(k * NC + c) * 256 + tid] = s;
    } else {
        sub[(k * NC + c) * 256 + 255] = 0.f;
    }
}

// ---------------- main GEMM with fused prefix + in-smem diagonal cumsum ----------------
// Ypart[c][b][t] = sum_{w in chunk c} M[t][w] z[b][w], M = diag-cumsum(Q).
// One 128-wide chunk per CTA (blockIdx.y = c); blockIdx.z = batch slice of NB rows.
// Loads raw Q tile; while loads are in flight, computes the diagonal entering prefix from
// g_sub; cumsums in smem; FMA loop.
template <int NB>
__global__ __launch_bounds__(256, 2) void skewgemm_kernel(const float* __restrict__ Q, int ld,
                                                          const float* __restrict__ z, int zld,
                                                          const float* __restrict__ sub,
                                                          float* __restrict__ Ypart, int Tdim) {
    extern __shared__ float sh[];
    float* sM = sh;                 // 128 x 132
    float* sz = sh + 128 * 132;     // NB x 132
    int k = blockIdx.x;
    int c = blockIdx.y;
    int b0 = blockIdx.z * NB;
    int t0 = k << 7;
    int w0 = c << 7;
    int NC = ld >> 7;
    int tx = threadIdx.x & 15, ty = threadIdx.x >> 4;
    int tid = threadIdx.x;
    const int NV = NB / 16;
    float acc[8][NV];
#pragma unroll
    for (int u = 0; u < 8; u++)
#pragma unroll
        for (int v = 0; v < NV; v++) acc[u][v] = 0.f;

    for (int idx = tid; idx < 128 * 32; idx += 256) {
        int row = idx >> 5, c4 = idx & 31;
        float4 m4 = *(const float4*)&Q[(size_t)(t0 + row) * ld + w0 + 4 * c4];
        *(float4*)&sM[row * 132 + 4 * c4] = m4;
    }
    for (int idx = tid; idx < NB * 32; idx += 256) {
        int b = idx >> 5, c4 = idx & 31;
        float4 z4 = *(const float4*)&z[(size_t)(b0 + b) * zld + w0 + 4 * c4];
        *(float4*)&sz[b * 132 + 4 * c4] = z4;
    }
    // ---- prefix for (k,c), overlapped with the tile loads above ----
    // global diag d = 128*(k-c) + (tid-127); earlier subtiles: k2<k any chunk, or k2==k c2<c.
    // chunk candidates per t-tile: q = k2-c2 in {d>>7, (d+127)>>7}.
    float pacc = 0.f;
    if (tid < 255) {
        int d = ((k - c) << 7) + (tid - 127);
        int qlo = d >> 7;
        int qhi = (d + 127) >> 7;
        int jlo = (d - (qlo << 7)) + 127;
        int jhi = (d - (qhi << 7)) + 127;
        for (int k2 = 0; k2 < k; k2++) {
            int c2 = k2 - qlo;
            if (c2 >= 0 && c2 < NC) pacc += sub[(k2 * NC + c2) * 256 + jlo];
            if (qhi != qlo) {
                c2 = k2 - qhi;
                if (c2 >= 0 && c2 < NC) pacc += sub[(k2 * NC + c2) * 256 + jhi];
            }
        }
        int c2 = k - qlo;
        if (c2 >= 0 && c2 < c) pacc += sub[(k * NC + c2) * 256 + jlo];
        if (qhi != qlo) {
            c2 = k - qhi;
            if (c2 >= 0 && c2 < c) pacc += sub[(k * NC + c2) * 256 + jhi];
        }
    }
    __syncthreads();
    // in-smem segmented diagonal cumsum on sM, seeded by pacc
    if (tid < 255) {
        int dl = tid - 127;
        float a = pacc;
#pragma unroll 4
        for (int row = 0; row < 128; row++) {
            int col = row - dl;
            if ((unsigned)col < 128u) {
                a += sM[row * 132 + col];
                sM[row * 132 + col] = a;
            }
        }
    }
    __syncthreads();
#pragma unroll 4
    for (int ww = 0; ww < 128; ww++) {
        float a[8], zb[NV];
#pragma unroll
        for (int u = 0; u < 8; u++) a[u] = sM[(tx + 16 * u) * 132 + ww];
#pragma unroll
        for (int v = 0; v < NV; v++) zb[v] = sz[(ty + 16 * v) * 132 + ww];
#pragma unroll
        for (int u = 0; u < 8; u++)
#pragma unroll
            for (int v = 0; v < NV; v++) acc[u][v] = fmaf(a[u], zb[v], acc[u][v]);
    }
#pragma unroll
    for (int u = 0; u < 8; u++) {
        int t = t0 + tx + 16 * u;
#pragma unroll
        for (int v = 0; v < NV; v++) {
            int b = b0 + ty + 16 * v;
            Ypart[((size_t)c * BATCH + b) * Tdim + t] = acc[u][v];
        }
    }
}

// ---------------- epilogue 1: reduce 8 partials, z2 = relu(da1*s + b1) * db2 (full 4096) -------
__global__ void epilogue1_kernel(const float* __restrict__ bias) {
    int i4 = blockIdx.x * 256 + threadIdx.x;
    if (i4 >= BATCH * LSZ / 4) return;
    const float4* Yp = (const float4*)g_Ypart;
    float4 s = Yp[i4];
#pragma unroll
    for (int k = 1; k < 8; k++) {
        float4 p = Yp[(size_t)k * (BATCH * LSZ / 4) + i4];
        s.x += p.x; s.y += p.y; s.z += p.z; s.w += p.w;
    }
    int t = (i4 * 4) & (LSZ - 1);
    float4 dav = *(const float4*)&g_da1[t];
    float4 bv  = *(const float4*)&bias[t];
    float4 db  = *(const float4*)&g_db2[t];
    float4 h;
    h.x = fmaxf(dav.x * s.x + bv.x, 0.f) * db.x;
    h.y = fmaxf(dav.y * s.y + bv.y, 0.f) * db.y;
    h.z = fmaxf(dav.z * s.z + bv.z, 0.f) * db.z;
    h.w = fmaxf(dav.w * s.w + bv.w, 0.f) * db.w;
    ((float4*)g_z2)[i4] = h;
}

// ---------------- fused epilogue2 + logits ----------------
// block b: h2[t] = relu(da2*sum_k Ypart[k][b][t] + b2[t]) into smem, then 10 warps
// each compute one class dot product over 512.
__global__ __launch_bounds__(512) void epilogits_kernel(const float* __restrict__ bias,
                                                        const float* __restrict__ W,
                                                        const float* __restrict__ bl,
                                                        float* __restrict__ out) {
    __shared__ float sh2[FCN];
    int b = blockIdx.x;
    int t = threadIdx.x;            // 512 threads = one t each
    float s = 0.f;
#pragma unroll
    for (int k = 0; k < 32; k++) s += g_Ypart[(size_t)k * BATCH * FCN + b * FCN + t];
    sh2[t] = fmaxf(g_da2[t] * s + bias[t], 0.f);
    __syncthreads();
    int cls = t >> 5;
    int lane = t & 31;
    if (cls < NCLS) {
        float acc = 0.f;
#pragma unroll
        for (int m = 0; m < 16; m++) {
            int j = lane + 32 * m;
            acc = fmaf(sh2[j], W[cls * FCN + j], acc);
        }
#pragma unroll
        for (int off = 16; off; off >>= 1) acc += __shfl_down_sync(0xffffffffu, acc, off);
        if (lane == 0) out[b * NCLS + cls] = acc + bl[cls];
    }
}

// ---------------- launch ----------------
extern "C" void kernel_launch(void* const* d_in, const int* in_sizes, int n_in,
                              void* d_out, int out_size) {
    const float* x    = (const float*)d_in[0];
    const float* G1   = (const float*)d_in[1];
    const float* H1   = (const float*)d_in[2];
    const float* sdA1 = (const float*)d_in[3];
    const float* sdB1 = (const float*)d_in[4];
    const float* b1   = (const float*)d_in[5];
    const float* G2   = (const float*)d_in[6];
    const float* H2   = (const float*)d_in[7];
    const float* sdA2 = (const float*)d_in[8];
    const float* sdB2 = (const float*)d_in[9];
    const float* b2   = (const float*)d_in[10];
    const float* W    = (const float*)d_in[11];
    const float* bl   = (const float*)d_in[12];
    float* out = (float*)d_out;

    const int QSM  = 128 * 132 * 4;               // 67584 (tile park; >= 2*R*132*4 for R<=48)
    const int GSM1 = (128 * 132 + 64 * 132) * 4;  // 101376 (NB=64)
    const int GSM2 = (128 * 132 + 32 * 132) * 4;  // 84480  (NB=32)

    cudaFuncSetAttribute(qgemm_kernel<R1>, cudaFuncAttributeMaxDynamicSharedMemorySize, QSM);
    cudaFuncSetAttribute(qgemm_kernel<R2>, cudaFuncAttributeMaxDynamicSharedMemorySize, QSM);
    cudaFuncSetAttribute(skewgemm_kernel<64>, cudaFuncAttributeMaxDynamicSharedMemorySize, GSM1);
    cudaFuncSetAttribute(skewgemm_kernel<32>, cudaFuncAttributeMaxDynamicSharedMemorySize, GSM2);

    float* Mbuf;  cudaGetSymbolAddress((void**)&Mbuf, g_M);
    float* Sub;   cudaGetSymbolAddress((void**)&Sub, g_sub);
    float* Ypart; cudaGetSymbolAddress((void**)&Ypart, g_Ypart);
    float* z1;    cudaGetSymbolAddress((void**)&z1, g_z1);
    float* z2;    cudaGetSymbolAddress((void**)&z2, g_z2);
    float* Gt1;   cudaGetSymbolAddress((void**)&Gt1, g_Gt1);
    float* Ht1;   cudaGetSymbolAddress((void**)&Ht1, g_Ht1);
    float* Gt2;   cudaGetSymbolAddress((void**)&Gt2, g_Gt2);
    float* Ht2;   cudaGetSymbolAddress((void**)&Ht2, g_Ht2);

    scan_kernel<<<4, 1024>>>(sdA1, sdB1, sdA2, sdB2);
    prep_kernel<<<1024, 256>>>(G1, H1, G2, H2, x);

    // ---- layer 1: strip 4096 x 1024 (input zero-padded beyond 1024); NC=8 ----
    qgemm_kernel<R1><<<dim3(8, 32), 256, QSM>>>(Gt1, Ht1, Mbuf, 1024, Sub);
    skewgemm_kernel<64><<<dim3(32, 8, 1), 256, GSM1>>>(Mbuf, 1024, z1, 1024, Sub, Ypart, LSZ);
    epilogue1_kernel<<<256, 256>>>(b1);

    // ---- layer 2: strip 512 x 4096 (only first 512 outputs used); NC=32 ----
    qgemm_kernel<R2><<<dim3(32, 4), 256, QSM>>>(Gt2, Ht2, Mbuf, 4096, Sub);
    skewgemm_kernel<32><<<dim3(4, 32, 2), 256, GSM2>>>(Mbuf, 4096, z2, 4096, Sub, Ypart, FCN);
    epilogits_kernel<<<64, 512>>>(b2, W, bl, out);
}